// round 1
// baseline (speedup 1.0000x reference)
#include <cuda_runtime.h>
#include <math.h>

#define NT 1024   // total peds
#define HD 128    // h_dim
#define ED 64     // embedding dim
#define SC 32     // scenes
#define PP 32     // peds per scene
#define B1D 512
#define B2D 1024
#define M1D 1024
#define TS 12
#define KM1 (HD + B2D)   // 1152

static __constant__ float c_dummy;  // (unused)
#define BN_INV_F 0.9999950000374997f

// ---------------- device state / scratch ----------------
static __device__ float g_h[NT * HD];
static __device__ float g_c[NT * HD];
static __device__ float g_h2[NT * HD];
static __device__ float g_lp[NT * 2];
static __device__ float g_din[NT * ED];
static __device__ float g_hpre[NT * B1D];
static __device__ float g_pool[NT * B2D];
static __device__ float g_mid[NT * M1D];
// folded weights
static __device__ float g_A[B1D], g_B[B1D], g_bias1[B1D];
static __device__ float g_Wb[B1D * HD];
static __device__ float g_W2[B2D * B1D], g_bias2[B2D];
static __device__ float g_M1w[M1D * KM1], g_bm1[M1D];
static __device__ float g_M2w[HD * M1D], g_bm2[HD];

// ---------------- prep kernels ----------------
__global__ void init_state(const float* __restrict__ h0, const float* __restrict__ c0,
                           const float* __restrict__ last_pos, const float* __restrict__ last_pos_rel,
                           const float* __restrict__ embW, const float* __restrict__ embb) {
    int idx = blockIdx.x * blockDim.x + threadIdx.x;
    if (idx < NT * HD) { g_h[idx] = h0[idx]; g_c[idx] = c0[idx]; }
    if (idx < NT * 2) g_lp[idx] = last_pos[idx];
    if (idx < NT * ED) {
        int n = idx / ED, e = idx % ED;
        g_din[idx] = last_pos_rel[n * 2] * embW[e * 2] +
                     last_pos_rel[n * 2 + 1] * embW[e * 2 + 1] + embb[e];
    }
}

// fold pp1: collapse spatial-embedding Linear into rank-2 direction term + h-term, fold BN scale
__global__ void fold_pp1(const float* __restrict__ pp1_W, const float* __restrict__ pp1_b,
                         const float* __restrict__ pp1_g, const float* __restrict__ pp1_be,
                         const float* __restrict__ sp_W, const float* __restrict__ sp_b) {
    int k = blockIdx.x * blockDim.x + threadIdx.x;
    if (k >= B1D) return;
    float s1 = BN_INV_F * pp1_g[k];
    const float* row = pp1_W + (size_t)k * (ED + HD);
    float sa = 0.f, sb = 0.f, sc = 0.f;
    for (int e = 0; e < ED; e++) {
        float w = row[e];
        sa += w * sp_W[e * 2];
        sb += w * sp_W[e * 2 + 1];
        sc += w * sp_b[e];
    }
    g_A[k] = sa * s1;
    g_B[k] = sb * s1;
    g_bias1[k] = (pp1_b[k] + sc) * s1 + pp1_be[k];
    for (int h = 0; h < HD; h++) g_Wb[k * HD + h] = row[ED + h] * s1;
}

// fold BN scale into a row-major weight matrix [rows, cols]; mode selects target
__global__ void fold_rows(const float* __restrict__ W, const float* __restrict__ b,
                          const float* __restrict__ g, const float* __restrict__ be, int mode) {
    float* Wout; float* bout; int rows, cols;
    if (mode == 0)      { Wout = g_W2;  bout = g_bias2; rows = B2D; cols = B1D; }
    else if (mode == 1) { Wout = g_M1w; bout = g_bm1;   rows = M1D; cols = KM1; }
    else                { Wout = g_M2w; bout = g_bm2;   rows = HD;  cols = M1D; }
    size_t total = (size_t)rows * cols;
    for (size_t idx = blockIdx.x * blockDim.x + threadIdx.x; idx < total;
         idx += (size_t)gridDim.x * blockDim.x) {
        int r = (int)(idx / cols);
        float s = BN_INV_F * g[r];
        Wout[idx] = W[idx] * s;
        if (idx % cols == 0) bout[r] = b[r] * s + be[r];
    }
}

// ---------------- LSTM step + pos head + next embedding ----------------
__global__ __launch_bounds__(128) void lstm_step(
    const float* __restrict__ Wih, const float* __restrict__ Whh,
    const float* __restrict__ bih, const float* __restrict__ bhh,
    const float* __restrict__ posW, const float* __restrict__ posb,
    const float* __restrict__ embW, const float* __restrict__ embb,
    float* __restrict__ out_t) {
    int n = blockIdx.x;
    int t = threadIdx.x;  // 128 threads
    __shared__ float din_s[ED];
    __shared__ float h_s[HD];
    __shared__ float red0[HD], red1[HD];
    __shared__ float rp[2];
    if (t < ED) din_s[t] = g_din[n * ED + t];
    h_s[t] = g_h[n * HD + t];
    __syncthreads();
    float gate[4];
#pragma unroll
    for (int q = 0; q < 4; q++) {
        int row = q * HD + t;
        float acc = bih[row] + bhh[row];
        const float* wi = Wih + (size_t)row * ED;
#pragma unroll 8
        for (int e = 0; e < ED; e++) acc = fmaf(din_s[e], wi[e], acc);
        const float* wh = Whh + (size_t)row * HD;
#pragma unroll 8
        for (int j = 0; j < HD; j++) acc = fmaf(h_s[j], wh[j], acc);
        gate[q] = acc;
    }
    float ig = 1.f / (1.f + expf(-gate[0]));
    float fg = 1.f / (1.f + expf(-gate[1]));
    float gg = tanhf(gate[2]);
    float og = 1.f / (1.f + expf(-gate[3]));
    float c2 = fg * g_c[n * HD + t] + ig * gg;
    float h2 = og * tanhf(c2);
    g_c[n * HD + t] = c2;
    g_h2[n * HD + t] = h2;
    red0[t] = h2 * posW[t];
    red1[t] = h2 * posW[HD + t];
    __syncthreads();
    for (int s = 64; s > 0; s >>= 1) {
        if (t < s) { red0[t] += red0[t + s]; red1[t] += red1[t + s]; }
        __syncthreads();
    }
    if (t < 2) {
        float v = ((t == 0) ? red0[0] : red1[0]) + posb[t];
        rp[t] = v;
        out_t[n * 2 + t] = v;        // predicted rel displacement
        g_lp[n * 2 + t] += v;        // curr = rel_pos + last_pos (becomes new last_pos)
    }
    __syncthreads();
    if (t < ED) {
        g_din[n * ED + t] = fmaf(rp[0], embW[t * 2], fmaf(rp[1], embW[t * 2 + 1], embb[t]));
    }
}

// ---------------- tiled GEMM family ----------------
// MODE 0: hpre = h2 @ Wb^T + bias1                        [1024 x 512], K=128
// MODE 1: pool = max_j relu(x1(s,i,j) @ W2^T + bias2)     groups=1024,  K=512 (x1 generated on the fly)
// MODE 2: mid  = relu(concat(h2,pool) @ M1^T + bm1)       [1024 x 1024], K=1152
// MODE 3: h    = relu(mid @ M2^T + bm2)                   [1024 x 128],  K=1024
template <int MODE>
__global__ __launch_bounds__(256) void tile_gemm() {
    constexpr int K   = (MODE == 0) ? HD : (MODE == 1) ? B1D : (MODE == 2) ? KM1 : M1D;
    constexpr int LDC = (MODE == 0) ? B1D : (MODE == 2) ? M1D : HD;
    const float* Wp = (MODE == 0) ? g_Wb : (MODE == 1) ? g_W2 : (MODE == 2) ? g_M1w : g_M2w;
    const float* bp = (MODE == 0) ? g_bias1 : (MODE == 1) ? g_bias2 : (MODE == 2) ? g_bm1 : g_bm2;
    float* outp = (MODE == 0) ? g_hpre : (MODE == 2) ? g_mid : g_h;

    int c0 = blockIdx.x * 128;
    int grp = blockIdx.y;
    int tid = threadIdx.x;
    int tx = tid & 31, ty = tid >> 5;

    __shared__ float a_s[32][64];
    __shared__ float w_s[64][129];
    __shared__ float relx[32], rely[32];
    __shared__ float As[B1D], Bs[B1D];

    int nbase = grp * 32;
    if (MODE == 1) {
        int s = grp >> 5, i = grp & 31;
        nbase = s * 32;
        if (tid < 32) {
            float dx = g_lp[(nbase + tid) * 2]     - g_lp[(nbase + i) * 2];
            float dy = g_lp[(nbase + tid) * 2 + 1] - g_lp[(nbase + i) * 2 + 1];
            float nrm = fmaxf(sqrtf(dx * dx + dy * dy), 1e-12f);
            relx[tid] = dx / nrm;
            rely[tid] = dy / nrm;
        }
        for (int idx = tid; idx < B1D; idx += 256) { As[idx] = g_A[idx]; Bs[idx] = g_B[idx]; }
    }

    float acc[4][4] = {};
    for (int k0 = 0; k0 < K; k0 += 64) {
        __syncthreads();
        for (int idx = tid; idx < 32 * 64; idx += 256) {
            int j = idx >> 6, k = idx & 63, kk = k0 + k;
            float v;
            if (MODE == 0) {
                v = g_h2[(nbase + j) * HD + kk];
            } else if (MODE == 1) {
                v = g_hpre[(nbase + j) * B1D + kk];
                v = fmaf(relx[j], As[kk], v);
                v = fmaf(rely[j], Bs[kk], v);
                v = fmaxf(v, 0.f);   // x1 = relu(folded pp1)
            } else if (MODE == 2) {
                v = (kk < HD) ? g_h2[(nbase + j) * HD + kk]
                              : g_pool[(nbase + j) * B2D + kk - HD];
            } else {
                v = g_mid[(nbase + j) * M1D + kk];
            }
            a_s[j][k] = v;
        }
        for (int idx = tid; idx < 128 * 64; idx += 256) {
            int c = idx >> 6, k = idx & 63;
            w_s[k][c] = Wp[(size_t)(c0 + c) * K + k0 + k];
        }
        __syncthreads();
#pragma unroll 4
        for (int k = 0; k < 64; k++) {
            float xr[4], wr[4];
#pragma unroll
            for (int jj = 0; jj < 4; jj++) xr[jj] = a_s[ty + jj * 8][k];
#pragma unroll
            for (int cc = 0; cc < 4; cc++) wr[cc] = w_s[k][tx + cc * 32];
#pragma unroll
            for (int jj = 0; jj < 4; jj++)
#pragma unroll
                for (int cc = 0; cc < 4; cc++) acc[jj][cc] = fmaf(xr[jj], wr[cc], acc[jj][cc]);
        }
    }
    __syncthreads();

    if (MODE == 1) {
        float* red = &a_s[0][0];  // reuse (needs 8*128 floats, a_s has 2048)
#pragma unroll
        for (int cc = 0; cc < 4; cc++) {
            int c = tx + cc * 32;
            float m = acc[0][cc];
#pragma unroll
            for (int jj = 1; jj < 4; jj++) m = fmaxf(m, acc[jj][cc]);
            red[ty * 128 + c] = m;
        }
        __syncthreads();
        for (int c = tid; c < 128; c += 256) {
            float m = red[c];
#pragma unroll
            for (int r = 1; r < 8; r++) m = fmaxf(m, red[r * 128 + c]);
            // max_j relu(x+b) == relu(max_j x + b)
            g_pool[(size_t)grp * B2D + c0 + c] = fmaxf(m + bp[c0 + c], 0.f);
        }
    } else {
#pragma unroll
        for (int jj = 0; jj < 4; jj++) {
            int n = nbase + ty + jj * 8;
#pragma unroll
            for (int cc = 0; cc < 4; cc++) {
                int c = c0 + tx + cc * 32;
                float v = acc[jj][cc] + bp[c];
                if (MODE != 0) v = fmaxf(v, 0.f);
                outp[(size_t)n * LDC + c] = v;
            }
        }
    }
}

// ---------------- host launch ----------------
extern "C" void kernel_launch(void* const* d_in, const int* in_sizes, int n_in,
                              void* d_out, int out_size) {
    const float* last_pos     = (const float*)d_in[0];
    const float* last_pos_rel = (const float*)d_in[1];
    const float* h0           = (const float*)d_in[2];
    const float* c0           = (const float*)d_in[3];
    // d_in[4] seq_start_end: scenes are uniform (arange*P) -> layout hardcoded
    const float* emb_W  = (const float*)d_in[5];
    const float* emb_b  = (const float*)d_in[6];
    const float* Wih    = (const float*)d_in[7];
    const float* Whh    = (const float*)d_in[8];
    const float* bih    = (const float*)d_in[9];
    const float* bhh    = (const float*)d_in[10];
    const float* pos_W  = (const float*)d_in[11];
    const float* pos_b  = (const float*)d_in[12];
    const float* sp_W   = (const float*)d_in[13];
    const float* sp_b   = (const float*)d_in[14];
    const float* pp1_W  = (const float*)d_in[15];
    const float* pp1_b  = (const float*)d_in[16];
    const float* pp1_g  = (const float*)d_in[17];
    const float* pp1_be = (const float*)d_in[18];
    const float* pp2_W  = (const float*)d_in[19];
    const float* pp2_b  = (const float*)d_in[20];
    const float* pp2_g  = (const float*)d_in[21];
    const float* pp2_be = (const float*)d_in[22];
    const float* m1_W   = (const float*)d_in[23];
    const float* m1_b   = (const float*)d_in[24];
    const float* m1_g   = (const float*)d_in[25];
    const float* m1_be  = (const float*)d_in[26];
    const float* m2_W   = (const float*)d_in[27];
    const float* m2_b   = (const float*)d_in[28];
    const float* m2_g   = (const float*)d_in[29];
    const float* m2_be  = (const float*)d_in[30];
    float* out = (float*)d_out;

    init_state<<<(NT * HD + 255) / 256, 256>>>(h0, c0, last_pos, last_pos_rel, emb_W, emb_b);
    fold_pp1<<<2, 256>>>(pp1_W, pp1_b, pp1_g, pp1_be, sp_W, sp_b);
    fold_rows<<<512, 256>>>(pp2_W, pp2_b, pp2_g, pp2_be, 0);
    fold_rows<<<512, 256>>>(m1_W, m1_b, m1_g, m1_be, 1);
    fold_rows<<<512, 256>>>(m2_W, m2_b, m2_g, m2_be, 2);

    for (int t = 0; t < TS; t++) {
        lstm_step<<<NT, 128>>>(Wih, Whh, bih, bhh, pos_W, pos_b, emb_W, emb_b,
                               out + (size_t)t * NT * 2);
        tile_gemm<0><<<dim3(B1D / 128, NT / 32), 256>>>();   // hpre
        tile_gemm<1><<<dim3(B2D / 128, NT), 256>>>();        // pool (dominant GEMM + max)
        tile_gemm<2><<<dim3(M1D / 128, NT / 32), 256>>>();   // m1
        tile_gemm<3><<<dim3(1, NT / 32), 256>>>();           // m2 -> new h
    }
    (void)in_sizes; (void)n_in; (void)out_size;
}

// round 2
// speedup vs baseline: 1.0015x; 1.0015x over previous
#include <cuda_runtime.h>
#include <math.h>

#define NT 1024   // total peds
#define HD 128    // h_dim
#define ED 64     // embedding dim
#define SC 32     // scenes
#define PP 32     // peds per scene
#define B1D 512
#define B2D 1024
#define M1D 1024
#define TS 12
#define KM1 (HD + B2D)   // 1152

static __constant__ float c_dummy;  // (unused)
#define BN_INV_F 0.9999950000374997f

// ---------------- device state / scratch ----------------
static __device__ float g_h[NT * HD];
static __device__ float g_c[NT * HD];
static __device__ float g_h2[NT * HD];
static __device__ float g_lp[NT * 2];
static __device__ float g_din[NT * ED];
static __device__ float g_hpre[NT * B1D];
static __device__ float g_pool[NT * B2D];
static __device__ float g_mid[NT * M1D];
// folded weights
static __device__ float g_A[B1D], g_B[B1D], g_bias1[B1D];
static __device__ float g_Wb[B1D * HD];
static __device__ float g_W2[B2D * B1D], g_bias2[B2D];
static __device__ float g_M1w[M1D * KM1], g_bm1[M1D];
static __device__ float g_M2w[HD * M1D], g_bm2[HD];

// ---------------- prep kernels ----------------
__global__ void init_state(const float* __restrict__ h0, const float* __restrict__ c0,
                           const float* __restrict__ last_pos, const float* __restrict__ last_pos_rel,
                           const float* __restrict__ embW, const float* __restrict__ embb) {
    int idx = blockIdx.x * blockDim.x + threadIdx.x;
    if (idx < NT * HD) { g_h[idx] = h0[idx]; g_c[idx] = c0[idx]; }
    if (idx < NT * 2) g_lp[idx] = last_pos[idx];
    if (idx < NT * ED) {
        int n = idx / ED, e = idx % ED;
        g_din[idx] = last_pos_rel[n * 2] * embW[e * 2] +
                     last_pos_rel[n * 2 + 1] * embW[e * 2 + 1] + embb[e];
    }
}

// fold pp1: collapse spatial-embedding Linear into rank-2 direction term + h-term, fold BN scale
__global__ void fold_pp1(const float* __restrict__ pp1_W, const float* __restrict__ pp1_b,
                         const float* __restrict__ pp1_g, const float* __restrict__ pp1_be,
                         const float* __restrict__ sp_W, const float* __restrict__ sp_b) {
    int k = blockIdx.x * blockDim.x + threadIdx.x;
    if (k >= B1D) return;
    float s1 = BN_INV_F * pp1_g[k];
    const float* row = pp1_W + (size_t)k * (ED + HD);
    float sa = 0.f, sb = 0.f, sc = 0.f;
    for (int e = 0; e < ED; e++) {
        float w = row[e];
        sa += w * sp_W[e * 2];
        sb += w * sp_W[e * 2 + 1];
        sc += w * sp_b[e];
    }
    g_A[k] = sa * s1;
    g_B[k] = sb * s1;
    g_bias1[k] = (pp1_b[k] + sc) * s1 + pp1_be[k];
    for (int h = 0; h < HD; h++) g_Wb[k * HD + h] = row[ED + h] * s1;
}

// fold BN scale into a row-major weight matrix [rows, cols]; mode selects target
__global__ void fold_rows(const float* __restrict__ W, const float* __restrict__ b,
                          const float* __restrict__ g, const float* __restrict__ be, int mode) {
    float* Wout; float* bout; int rows, cols;
    if (mode == 0)      { Wout = g_W2;  bout = g_bias2; rows = B2D; cols = B1D; }
    else if (mode == 1) { Wout = g_M1w; bout = g_bm1;   rows = M1D; cols = KM1; }
    else                { Wout = g_M2w; bout = g_bm2;   rows = HD;  cols = M1D; }
    size_t total = (size_t)rows * cols;
    for (size_t idx = blockIdx.x * blockDim.x + threadIdx.x; idx < total;
         idx += (size_t)gridDim.x * blockDim.x) {
        int r = (int)(idx / cols);
        float s = BN_INV_F * g[r];
        Wout[idx] = W[idx] * s;
        if (idx % cols == 0) bout[r] = b[r] * s + be[r];
    }
}

// ---------------- LSTM step + pos head + next embedding ----------------
__global__ __launch_bounds__(128) void lstm_step(
    const float* __restrict__ Wih, const float* __restrict__ Whh,
    const float* __restrict__ bih, const float* __restrict__ bhh,
    const float* __restrict__ posW, const float* __restrict__ posb,
    const float* __restrict__ embW, const float* __restrict__ embb,
    float* __restrict__ out_t) {
    int n = blockIdx.x;
    int t = threadIdx.x;  // 128 threads
    __shared__ float din_s[ED];
    __shared__ float h_s[HD];
    __shared__ float red0[HD], red1[HD];
    __shared__ float rp[2];
    if (t < ED) din_s[t] = g_din[n * ED + t];
    h_s[t] = g_h[n * HD + t];
    __syncthreads();
    float gate[4];
#pragma unroll
    for (int q = 0; q < 4; q++) {
        int row = q * HD + t;
        float acc = bih[row] + bhh[row];
        const float* wi = Wih + (size_t)row * ED;
#pragma unroll 8
        for (int e = 0; e < ED; e++) acc = fmaf(din_s[e], wi[e], acc);
        const float* wh = Whh + (size_t)row * HD;
#pragma unroll 8
        for (int j = 0; j < HD; j++) acc = fmaf(h_s[j], wh[j], acc);
        gate[q] = acc;
    }
    float ig = 1.f / (1.f + expf(-gate[0]));
    float fg = 1.f / (1.f + expf(-gate[1]));
    float gg = tanhf(gate[2]);
    float og = 1.f / (1.f + expf(-gate[3]));
    float c2 = fg * g_c[n * HD + t] + ig * gg;
    float h2 = og * tanhf(c2);
    g_c[n * HD + t] = c2;
    g_h2[n * HD + t] = h2;
    red0[t] = h2 * posW[t];
    red1[t] = h2 * posW[HD + t];
    __syncthreads();
    for (int s = 64; s > 0; s >>= 1) {
        if (t < s) { red0[t] += red0[t + s]; red1[t] += red1[t + s]; }
        __syncthreads();
    }
    if (t < 2) {
        float v = ((t == 0) ? red0[0] : red1[0]) + posb[t];
        rp[t] = v;
        out_t[n * 2 + t] = v;        // predicted rel displacement
        g_lp[n * 2 + t] += v;        // curr = rel_pos + last_pos (becomes new last_pos)
    }
    __syncthreads();
    if (t < ED) {
        g_din[n * ED + t] = fmaf(rp[0], embW[t * 2], fmaf(rp[1], embW[t * 2 + 1], embb[t]));
    }
}

// ---------------- tiled GEMM family ----------------
// MODE 0: hpre = h2 @ Wb^T + bias1                        [1024 x 512], K=128
// MODE 1: pool = max_j relu(x1(s,i,j) @ W2^T + bias2)     groups=1024,  K=512 (x1 generated on the fly)
// MODE 2: mid  = relu(concat(h2,pool) @ M1^T + bm1)       [1024 x 1024], K=1152
// MODE 3: h    = relu(mid @ M2^T + bm2)                   [1024 x 128],  K=1024
template <int MODE>
__global__ __launch_bounds__(256) void tile_gemm() {
    constexpr int K   = (MODE == 0) ? HD : (MODE == 1) ? B1D : (MODE == 2) ? KM1 : M1D;
    constexpr int LDC = (MODE == 0) ? B1D : (MODE == 2) ? M1D : HD;
    const float* Wp = (MODE == 0) ? g_Wb : (MODE == 1) ? g_W2 : (MODE == 2) ? g_M1w : g_M2w;
    const float* bp = (MODE == 0) ? g_bias1 : (MODE == 1) ? g_bias2 : (MODE == 2) ? g_bm1 : g_bm2;
    float* outp = (MODE == 0) ? g_hpre : (MODE == 2) ? g_mid : g_h;

    int c0 = blockIdx.x * 128;
    int grp = blockIdx.y;
    int tid = threadIdx.x;
    int tx = tid & 31, ty = tid >> 5;

    __shared__ float a_s[32][64];
    __shared__ float w_s[64][129];
    __shared__ float relx[32], rely[32];
    __shared__ float As[B1D], Bs[B1D];

    int nbase = grp * 32;
    if (MODE == 1) {
        int s = grp >> 5, i = grp & 31;
        nbase = s * 32;
        if (tid < 32) {
            float dx = g_lp[(nbase + tid) * 2]     - g_lp[(nbase + i) * 2];
            float dy = g_lp[(nbase + tid) * 2 + 1] - g_lp[(nbase + i) * 2 + 1];
            float nrm = fmaxf(sqrtf(dx * dx + dy * dy), 1e-12f);
            relx[tid] = dx / nrm;
            rely[tid] = dy / nrm;
        }
        for (int idx = tid; idx < B1D; idx += 256) { As[idx] = g_A[idx]; Bs[idx] = g_B[idx]; }
    }

    float acc[4][4] = {};
    for (int k0 = 0; k0 < K; k0 += 64) {
        __syncthreads();
        for (int idx = tid; idx < 32 * 64; idx += 256) {
            int j = idx >> 6, k = idx & 63, kk = k0 + k;
            float v;
            if (MODE == 0) {
                v = g_h2[(nbase + j) * HD + kk];
            } else if (MODE == 1) {
                v = g_hpre[(nbase + j) * B1D + kk];
                v = fmaf(relx[j], As[kk], v);
                v = fmaf(rely[j], Bs[kk], v);
                v = fmaxf(v, 0.f);   // x1 = relu(folded pp1)
            } else if (MODE == 2) {
                v = (kk < HD) ? g_h2[(nbase + j) * HD + kk]
                              : g_pool[(nbase + j) * B2D + kk - HD];
            } else {
                v = g_mid[(nbase + j) * M1D + kk];
            }
            a_s[j][k] = v;
        }
        for (int idx = tid; idx < 128 * 64; idx += 256) {
            int c = idx >> 6, k = idx & 63;
            w_s[k][c] = Wp[(size_t)(c0 + c) * K + k0 + k];
        }
        __syncthreads();
#pragma unroll 4
        for (int k = 0; k < 64; k++) {
            float xr[4], wr[4];
#pragma unroll
            for (int jj = 0; jj < 4; jj++) xr[jj] = a_s[ty + jj * 8][k];
#pragma unroll
            for (int cc = 0; cc < 4; cc++) wr[cc] = w_s[k][tx + cc * 32];
#pragma unroll
            for (int jj = 0; jj < 4; jj++)
#pragma unroll
                for (int cc = 0; cc < 4; cc++) acc[jj][cc] = fmaf(xr[jj], wr[cc], acc[jj][cc]);
        }
    }
    __syncthreads();

    if (MODE == 1) {
        float* red = &a_s[0][0];  // reuse (needs 8*128 floats, a_s has 2048)
#pragma unroll
        for (int cc = 0; cc < 4; cc++) {
            int c = tx + cc * 32;
            float m = acc[0][cc];
#pragma unroll
            for (int jj = 1; jj < 4; jj++) m = fmaxf(m, acc[jj][cc]);
            red[ty * 128 + c] = m;
        }
        __syncthreads();
        for (int c = tid; c < 128; c += 256) {
            float m = red[c];
#pragma unroll
            for (int r = 1; r < 8; r++) m = fmaxf(m, red[r * 128 + c]);
            // max_j relu(x+b) == relu(max_j x + b)
            g_pool[(size_t)grp * B2D + c0 + c] = fmaxf(m + bp[c0 + c], 0.f);
        }
    } else {
#pragma unroll
        for (int jj = 0; jj < 4; jj++) {
            int n = nbase + ty + jj * 8;
#pragma unroll
            for (int cc = 0; cc < 4; cc++) {
                int c = c0 + tx + cc * 32;
                float v = acc[jj][cc] + bp[c];
                if (MODE != 0) v = fmaxf(v, 0.f);
                outp[(size_t)n * LDC + c] = v;
            }
        }
    }
}

// ---------------- host launch ----------------
extern "C" void kernel_launch(void* const* d_in, const int* in_sizes, int n_in,
                              void* d_out, int out_size) {
    const float* last_pos     = (const float*)d_in[0];
    const float* last_pos_rel = (const float*)d_in[1];
    const float* h0           = (const float*)d_in[2];
    const float* c0           = (const float*)d_in[3];
    // d_in[4] seq_start_end: scenes are uniform (arange*P) -> layout hardcoded
    const float* emb_W  = (const float*)d_in[5];
    const float* emb_b  = (const float*)d_in[6];
    const float* Wih    = (const float*)d_in[7];
    const float* Whh    = (const float*)d_in[8];
    const float* bih    = (const float*)d_in[9];
    const float* bhh    = (const float*)d_in[10];
    const float* pos_W  = (const float*)d_in[11];
    const float* pos_b  = (const float*)d_in[12];
    const float* sp_W   = (const float*)d_in[13];
    const float* sp_b   = (const float*)d_in[14];
    const float* pp1_W  = (const float*)d_in[15];
    const float* pp1_b  = (const float*)d_in[16];
    const float* pp1_g  = (const float*)d_in[17];
    const float* pp1_be = (const float*)d_in[18];
    const float* pp2_W  = (const float*)d_in[19];
    const float* pp2_b  = (const float*)d_in[20];
    const float* pp2_g  = (const float*)d_in[21];
    const float* pp2_be = (const float*)d_in[22];
    const float* m1_W   = (const float*)d_in[23];
    const float* m1_b   = (const float*)d_in[24];
    const float* m1_g   = (const float*)d_in[25];
    const float* m1_be  = (const float*)d_in[26];
    const float* m2_W   = (const float*)d_in[27];
    const float* m2_b   = (const float*)d_in[28];
    const float* m2_g   = (const float*)d_in[29];
    const float* m2_be  = (const float*)d_in[30];
    float* out = (float*)d_out;

    init_state<<<(NT * HD + 255) / 256, 256>>>(h0, c0, last_pos, last_pos_rel, emb_W, emb_b);
    fold_pp1<<<2, 256>>>(pp1_W, pp1_b, pp1_g, pp1_be, sp_W, sp_b);
    fold_rows<<<512, 256>>>(pp2_W, pp2_b, pp2_g, pp2_be, 0);
    fold_rows<<<512, 256>>>(m1_W, m1_b, m1_g, m1_be, 1);
    fold_rows<<<512, 256>>>(m2_W, m2_b, m2_g, m2_be, 2);

    for (int t = 0; t < TS; t++) {
        lstm_step<<<NT, 128>>>(Wih, Whh, bih, bhh, pos_W, pos_b, emb_W, emb_b,
                               out + (size_t)t * NT * 2);
        tile_gemm<0><<<dim3(B1D / 128, NT / 32), 256>>>();   // hpre
        tile_gemm<1><<<dim3(B2D / 128, NT), 256>>>();        // pool (dominant GEMM + max)
        tile_gemm<2><<<dim3(M1D / 128, NT / 32), 256>>>();   // m1
        tile_gemm<3><<<dim3(1, NT / 32), 256>>>();           // m2 -> new h
    }
    (void)in_sizes; (void)n_in; (void)out_size;
}

// round 4
// speedup vs baseline: 2.7779x; 2.7738x over previous
#include <cuda_runtime.h>
#include <cuda_bf16.h>
#include <mma.h>
#include <stdint.h>
#include <math.h>

using namespace nvcuda;

#define NT 1024
#define HD 128
#define ED 64
#define SC 32
#define PP 32
#define B1D 512
#define B2D 1024
#define M1D 1024
#define TS 12
#define KM1 (HD + B2D)   // 1152
#define BN_INV_F 0.9999950000374997f

// ---------------- device state / scratch ----------------
static __device__ float g_h[NT * HD];
static __device__ float g_c[NT * HD];
static __device__ float g_h2[NT * HD];
static __device__ float g_lp[NT * 2];
static __device__ float g_din[NT * ED];
static __device__ float g_hpre[NT * B1D];
static __device__ float g_pool[NT * B2D];
static __device__ float g_mid[NT * M1D];
static __device__ float g_gates[NT * 4 * HD];
// folded scalar weights
static __device__ float g_A[B1D], g_B[B1D], g_bias1[B1D];
static __device__ float g_Wb[B1D * HD];
static __device__ float g_bias2[B2D], g_bm1[M1D];
static __device__ float g_M2w[HD * M1D], g_bm2[HD];
static __device__ float g_LW[4 * HD * 192], g_Lb[4 * HD];
// bf16 hi/lo split weights, row-major [c][k]
static __device__ __nv_bfloat16 g_W2h[B2D * B1D], g_W2l[B2D * B1D];
static __device__ __nv_bfloat16 g_M1h[M1D * KM1], g_M1l[M1D * KM1];

// ---------------- helpers ----------------
__device__ __forceinline__ uint32_t pack_bf(float v0, float v1, uint32_t* lo) {
    __nv_bfloat16 h0 = __float2bfloat16(v0), h1 = __float2bfloat16(v1);
    __nv_bfloat16 l0 = __float2bfloat16(v0 - __bfloat162float(h0));
    __nv_bfloat16 l1 = __float2bfloat16(v1 - __bfloat162float(h1));
    *lo = ((uint32_t)__bfloat16_as_ushort(l1) << 16) | __bfloat16_as_ushort(l0);
    return ((uint32_t)__bfloat16_as_ushort(h1) << 16) | __bfloat16_as_ushort(h0);
}

// ---------------- prep kernels (run once per launch) ----------------
__global__ void init_state(const float* __restrict__ h0, const float* __restrict__ c0,
                           const float* __restrict__ last_pos, const float* __restrict__ last_pos_rel,
                           const float* __restrict__ embW, const float* __restrict__ embb) {
    int idx = blockIdx.x * blockDim.x + threadIdx.x;
    if (idx < NT * HD) { g_h[idx] = h0[idx]; g_c[idx] = c0[idx]; }
    if (idx < NT * 2) g_lp[idx] = last_pos[idx];
    if (idx < NT * ED) {
        int n = idx / ED, e = idx % ED;
        g_din[idx] = last_pos_rel[n * 2] * embW[e * 2] +
                     last_pos_rel[n * 2 + 1] * embW[e * 2 + 1] + embb[e];
    }
}

__global__ void fold_pp1(const float* __restrict__ pp1_W, const float* __restrict__ pp1_b,
                         const float* __restrict__ pp1_g, const float* __restrict__ pp1_be,
                         const float* __restrict__ sp_W, const float* __restrict__ sp_b) {
    int k = blockIdx.x * blockDim.x + threadIdx.x;
    if (k >= B1D) return;
    float s1 = BN_INV_F * pp1_g[k];
    const float* row = pp1_W + (size_t)k * (ED + HD);
    float sa = 0.f, sb = 0.f, sc = 0.f;
    for (int e = 0; e < ED; e++) {
        float w = row[e];
        sa += w * sp_W[e * 2]; sb += w * sp_W[e * 2 + 1]; sc += w * sp_b[e];
    }
    g_A[k] = sa * s1; g_B[k] = sb * s1;
    g_bias1[k] = (pp1_b[k] + sc) * s1 + pp1_be[k];
    for (int h = 0; h < HD; h++) g_Wb[k * HD + h] = row[ED + h] * s1;
}

__global__ void fold_m2(const float* __restrict__ W, const float* __restrict__ b,
                        const float* __restrict__ g, const float* __restrict__ be) {
    for (int idx = blockIdx.x * blockDim.x + threadIdx.x; idx < HD * M1D; idx += gridDim.x * blockDim.x) {
        int r = idx / M1D;
        float s = BN_INV_F * g[r];
        g_M2w[idx] = W[idx] * s;
        if (idx % M1D == 0) g_bm2[r] = b[r] * s + be[r];
    }
}

__global__ void fold_LW(const float* __restrict__ Wih, const float* __restrict__ Whh,
                        const float* __restrict__ bih, const float* __restrict__ bhh) {
    for (int idx = blockIdx.x * blockDim.x + threadIdx.x; idx < 512 * 192; idx += gridDim.x * blockDim.x) {
        int r = idx / 192, cc = idx % 192;
        g_LW[idx] = (cc < 64) ? Wih[r * 64 + cc] : Whh[r * 128 + cc - 64];
        if (cc == 0) g_Lb[r] = bih[r] + bhh[r];
    }
}

// split weights into bf16 hi/lo, fold BN scale. WM=0: W2 (K=512), WM=1: m1 (K=1152)
template <int WM>
__global__ void prep_wB(const float* __restrict__ W, const float* __restrict__ b,
                        const float* __restrict__ g, const float* __restrict__ be) {
    constexpr int K = WM ? KM1 : B1D;
    constexpr int ROWS = WM ? M1D : B2D;
    __nv_bfloat16* oh = WM ? g_M1h : g_W2h;
    __nv_bfloat16* ol = WM ? g_M1l : g_W2l;
    float* bo = WM ? g_bm1 : g_bias2;
    int total = ROWS * (K / 2);
    for (int p = blockIdx.x * blockDim.x + threadIdx.x; p < total; p += gridDim.x * blockDim.x) {
        int c = p / (K / 2), kp = p % (K / 2), k = kp * 2;
        float s = BN_INV_F * g[c];
        float v0 = W[(size_t)c * K + k] * s, v1 = W[(size_t)c * K + k + 1] * s;
        uint32_t lo, hi = pack_bf(v0, v1, &lo);
        *(uint32_t*)(oh + (size_t)c * K + k) = hi;
        *(uint32_t*)(ol + (size_t)c * K + k) = lo;
        if (kp == 0) bo[c] = b[c] * s + be[c];
    }
}

// ---------------- SIMT GEMM: MODE 0 hpre(K=128), 1 m2(K=1024), 2 gates(K=192) ----------------
template <int MODE>
__global__ __launch_bounds__(256) void tile_gemm() {
    constexpr int K = (MODE == 0) ? HD : (MODE == 1) ? M1D : 192;
    constexpr int LDC = (MODE == 0) ? B1D : (MODE == 1) ? HD : 512;
    const float* Wp = (MODE == 0) ? g_Wb : (MODE == 1) ? g_M2w : g_LW;
    const float* bp = (MODE == 0) ? g_bias1 : (MODE == 1) ? g_bm2 : g_Lb;
    float* outp = (MODE == 0) ? g_hpre : (MODE == 1) ? g_h : g_gates;
    int c0 = blockIdx.x * 128, grp = blockIdx.y, tid = threadIdx.x;
    int tx = tid & 31, ty = tid >> 5;
    __shared__ float a_s[32][64];
    __shared__ float w_s[64][129];
    int nbase = grp * 32;
    float acc[4][4] = {};
    for (int k0 = 0; k0 < K; k0 += 64) {
        __syncthreads();
        for (int idx = tid; idx < 32 * 64; idx += 256) {
            int j = idx >> 6, k = idx & 63, kk = k0 + k;
            float v;
            if (MODE == 0) v = g_h2[(nbase + j) * HD + kk];
            else if (MODE == 1) v = g_mid[(size_t)(nbase + j) * M1D + kk];
            else v = (kk < 64) ? g_din[(nbase + j) * ED + kk] : g_h[(nbase + j) * HD + kk - 64];
            a_s[j][k] = v;
        }
        for (int idx = tid; idx < 128 * 64; idx += 256) {
            int c = idx >> 6, k = idx & 63;
            w_s[k][c] = Wp[(size_t)(c0 + c) * K + k0 + k];
        }
        __syncthreads();
#pragma unroll 4
        for (int k = 0; k < 64; k++) {
            float xr[4], wr[4];
#pragma unroll
            for (int jj = 0; jj < 4; jj++) xr[jj] = a_s[ty + jj * 8][k];
#pragma unroll
            for (int cc = 0; cc < 4; cc++) wr[cc] = w_s[k][tx + cc * 32];
#pragma unroll
            for (int jj = 0; jj < 4; jj++)
#pragma unroll
                for (int cc = 0; cc < 4; cc++) acc[jj][cc] = fmaf(xr[jj], wr[cc], acc[jj][cc]);
        }
    }
#pragma unroll
    for (int jj = 0; jj < 4; jj++) {
        int n = nbase + ty + jj * 8;
#pragma unroll
        for (int cc = 0; cc < 4; cc++) {
            int c = c0 + tx + cc * 32;
            float v = acc[jj][cc] + bp[c];
            if (MODE == 1) v = fmaxf(v, 0.f);
            outp[(size_t)n * LDC + c] = v;
        }
    }
}

// ---------------- LSTM pointwise (after gates GEMM) ----------------
__global__ __launch_bounds__(128) void lstm_point(
    const float* __restrict__ posW, const float* __restrict__ posb,
    const float* __restrict__ embW, const float* __restrict__ embb,
    float* __restrict__ out_t) {
    int n = blockIdx.x, t = threadIdx.x;
    __shared__ float red0[HD], red1[HD], rp[2];
    float gi = g_gates[n * 512 + 0 * HD + t];
    float gf = g_gates[n * 512 + 1 * HD + t];
    float gg = g_gates[n * 512 + 2 * HD + t];
    float go = g_gates[n * 512 + 3 * HD + t];
    float ig = 1.f / (1.f + expf(-gi));
    float fg = 1.f / (1.f + expf(-gf));
    float gv = tanhf(gg);
    float og = 1.f / (1.f + expf(-go));
    float c2 = fg * g_c[n * HD + t] + ig * gv;
    float h2 = og * tanhf(c2);
    g_c[n * HD + t] = c2;
    g_h2[n * HD + t] = h2;
    red0[t] = h2 * posW[t]; red1[t] = h2 * posW[HD + t];
    __syncthreads();
    for (int s = 64; s > 0; s >>= 1) {
        if (t < s) { red0[t] += red0[t + s]; red1[t] += red1[t + s]; }
        __syncthreads();
    }
    if (t < 2) {
        float v = ((t == 0) ? red0[0] : red1[0]) + posb[t];
        rp[t] = v;
        out_t[n * 2 + t] = v;
        g_lp[n * 2 + t] += v;
    }
    __syncthreads();
    if (t < ED) g_din[n * ED + t] = fmaf(rp[0], embW[t * 2], fmaf(rp[1], embW[t * 2 + 1], embb[t]));
}

// ---------------- wmma tensor GEMM (bf16 hi/lo 3-pass) ----------------
// GM=0: pool. grid(8 nb, 256): blockIdx.y = s*8+ib; M=128 rows = 4 i (ib*4..) x 32 j; K=512.
//       epilogue: max over j per i -> relu(max + bias2) -> g_pool.
// GM=1: m1. grid(8 nb, 8 mb): M=128 peds, K=1152; epilogue relu(bias) -> g_mid.
#define SMEM_W (4 * 128 * 72 * 2 + 2 * 128 * 4)   // stage (73728) + rxs/rys (1024)

template <int GM>
__global__ __launch_bounds__(256) void wmma_gemm() {
    constexpr int KC = GM ? 18 : 8;
    constexpr int KTOT = GM ? KM1 : B1D;
    extern __shared__ __align__(16) char smraw[];
    __nv_bfloat16* a_h = (__nv_bfloat16*)smraw;
    __nv_bfloat16* a_l = a_h + 128 * 72;
    __nv_bfloat16* w_h = a_l + 128 * 72;
    __nv_bfloat16* w_l = w_h + 128 * 72;
    float* rxs = (float*)(w_l + 128 * 72);
    float* rys = rxs + 128;
    float* c_s = (float*)smraw;   // epilogue reuse: 128x136 fp32 = 69632 < 73728

    int tid = threadIdx.x, w = tid >> 5;
    int nb = blockIdx.x, grp = blockIdx.y;
    const __nv_bfloat16* Wh_g = GM ? g_M1h : g_W2h;
    const __nv_bfloat16* Wl_g = GM ? g_M1l : g_W2l;

    int s = 0, ib = 0;
    if (GM == 0) {
        s = grp >> 3; ib = grp & 7;
        if (tid < 128) {
            int i = ib * 4 + (tid >> 5), j = tid & 31;
            float dx = g_lp[(s * 32 + j) * 2]     - g_lp[(s * 32 + i) * 2];
            float dy = g_lp[(s * 32 + j) * 2 + 1] - g_lp[(s * 32 + i) * 2 + 1];
            float nrm = fmaxf(sqrtf(dx * dx + dy * dy), 1e-12f);
            rxs[tid] = dx / nrm; rys[tid] = dy / nrm;
        }
    }

    wmma::fragment<wmma::accumulator, 16, 16, 16, float> acc[8];
#pragma unroll
    for (int mf = 0; mf < 8; mf++) wmma::fill_fragment(acc[mf], 0.f);

    for (int c = 0; c < KC; c++) {
        __syncthreads();
        // ---- stage A: 128 rows x 32 k-pairs, fp32 -> bf16 hi/lo ----
        for (int p = tid; p < 4096; p += 256) {
            int m = p >> 5, kp = p & 31, k = c * 64 + kp * 2;
            float v0, v1;
            if (GM == 0) {
                int pj = s * 32 + (m & 31);
                float rx = rxs[m], ry = rys[m];
                v0 = fmaxf(g_hpre[(size_t)pj * B1D + k]     + rx * g_A[k]     + ry * g_B[k], 0.f);
                v1 = fmaxf(g_hpre[(size_t)pj * B1D + k + 1] + rx * g_A[k + 1] + ry * g_B[k + 1], 0.f);
            } else {
                int ped = grp * 128 + m;
                if (k < HD) { v0 = g_h2[ped * HD + k]; v1 = g_h2[ped * HD + k + 1]; }
                else { v0 = g_pool[(size_t)ped * B2D + k - HD]; v1 = g_pool[(size_t)ped * B2D + k - HD + 1]; }
            }
            uint32_t lo, hi = pack_bf(v0, v1, &lo);
            *(uint32_t*)(a_h + m * 72 + kp * 2) = hi;
            *(uint32_t*)(a_l + m * 72 + kp * 2) = lo;
        }
        // ---- stage W: 128 rows x 64 k (bf16, vectorized) ----
        for (int p = tid; p < 1024; p += 256) {
            int r = p >> 3, k8 = p & 7;
            size_t off = (size_t)(nb * 128 + r) * KTOT + c * 64 + k8 * 8;
            *(uint4*)(w_h + r * 72 + k8 * 8) = *(const uint4*)(Wh_g + off);
            *(uint4*)(w_l + r * 72 + k8 * 8) = *(const uint4*)(Wl_g + off);
        }
        __syncthreads();
        // ---- compute: warp w owns 16 output cols ----
#pragma unroll
        for (int ks = 0; ks < 4; ks++) {
            wmma::fragment<wmma::matrix_b, 16, 16, 16, __nv_bfloat16, wmma::col_major> bh, bl;
            wmma::load_matrix_sync(bh, w_h + w * 16 * 72 + ks * 16, 72);
            wmma::load_matrix_sync(bl, w_l + w * 16 * 72 + ks * 16, 72);
#pragma unroll
            for (int mf = 0; mf < 8; mf++) {
                wmma::fragment<wmma::matrix_a, 16, 16, 16, __nv_bfloat16, wmma::row_major> ah, al;
                wmma::load_matrix_sync(ah, a_h + mf * 16 * 72 + ks * 16, 72);
                wmma::load_matrix_sync(al, a_l + mf * 16 * 72 + ks * 16, 72);
                wmma::mma_sync(acc[mf], ah, bh, acc[mf]);
                wmma::mma_sync(acc[mf], ah, bl, acc[mf]);
                wmma::mma_sync(acc[mf], al, bh, acc[mf]);
            }
        }
    }
    __syncthreads();
#pragma unroll
    for (int mf = 0; mf < 8; mf++)
        wmma::store_matrix_sync(c_s + mf * 16 * 136 + w * 16, acc[mf], 136, wmma::mem_row_major);
    __syncthreads();

    if (GM == 0) {
        // max over 32 j-rows per i, then relu(max + bias)
        for (int p = tid; p < 512; p += 256) {
            int il = p >> 7, cc = p & 127;
            float m = c_s[(il * 32) * 136 + cc];
#pragma unroll 8
            for (int r = 1; r < 32; r++) m = fmaxf(m, c_s[(il * 32 + r) * 136 + cc]);
            int col = nb * 128 + cc;
            g_pool[(size_t)(s * 32 + ib * 4 + il) * B2D + col] = fmaxf(m + g_bias2[col], 0.f);
        }
    } else {
        for (int p = tid; p < 16384; p += 256) {
            int r = p >> 7, cc = p & 127;
            int col = nb * 128 + cc;
            g_mid[(size_t)(grp * 128 + r) * M1D + col] = fmaxf(c_s[r * 136 + cc] + g_bm1[col], 0.f);
        }
    }
}

// ---------------- host launch ----------------
extern "C" void kernel_launch(void* const* d_in, const int* in_sizes, int n_in,
                              void* d_out, int out_size) {
    const float* last_pos     = (const float*)d_in[0];
    const float* last_pos_rel = (const float*)d_in[1];
    const float* h0  = (const float*)d_in[2];
    const float* c0  = (const float*)d_in[3];
    const float* emb_W = (const float*)d_in[5];
    const float* emb_b = (const float*)d_in[6];
    const float* Wih = (const float*)d_in[7];
    const float* Whh = (const float*)d_in[8];
    const float* bih = (const float*)d_in[9];
    const float* bhh = (const float*)d_in[10];
    const float* pos_W = (const float*)d_in[11];
    const float* pos_b = (const float*)d_in[12];
    const float* sp_W = (const float*)d_in[13];
    const float* sp_b = (const float*)d_in[14];
    const float* pp1_W = (const float*)d_in[15];
    const float* pp1_b = (const float*)d_in[16];
    const float* pp1_g = (const float*)d_in[17];
    const float* pp1_be = (const float*)d_in[18];
    const float* pp2_W = (const float*)d_in[19];
    const float* pp2_b = (const float*)d_in[20];
    const float* pp2_g = (const float*)d_in[21];
    const float* pp2_be = (const float*)d_in[22];
    const float* m1_W = (const float*)d_in[23];
    const float* m1_b = (const float*)d_in[24];
    const float* m1_g = (const float*)d_in[25];
    const float* m1_be = (const float*)d_in[26];
    const float* m2_W = (const float*)d_in[27];
    const float* m2_b = (const float*)d_in[28];
    const float* m2_g = (const float*)d_in[29];
    const float* m2_be = (const float*)d_in[30];
    float* out = (float*)d_out;

    cudaFuncSetAttribute(wmma_gemm<0>, cudaFuncAttributeMaxDynamicSharedMemorySize, SMEM_W);
    cudaFuncSetAttribute(wmma_gemm<1>, cudaFuncAttributeMaxDynamicSharedMemorySize, SMEM_W);

    init_state<<<(NT * HD + 255) / 256, 256>>>(h0, c0, last_pos, last_pos_rel, emb_W, emb_b);
    fold_pp1<<<2, 256>>>(pp1_W, pp1_b, pp1_g, pp1_be, sp_W, sp_b);
    fold_m2<<<128, 256>>>(m2_W, m2_b, m2_g, m2_be);
    fold_LW<<<96, 256>>>(Wih, Whh, bih, bhh);
    prep_wB<0><<<512, 256>>>(pp2_W, pp2_b, pp2_g, pp2_be);
    prep_wB<1><<<512, 256>>>(m1_W, m1_b, m1_g, m1_be);

    for (int t = 0; t < TS; t++) {
        tile_gemm<2><<<dim3(4, NT / 32), 256>>>();               // LSTM gates GEMM
        lstm_point<<<NT, 128>>>(pos_W, pos_b, emb_W, emb_b, out + (size_t)t * NT * 2);
        tile_gemm<0><<<dim3(4, NT / 32), 256>>>();               // hpre
        wmma_gemm<0><<<dim3(8, SC * 8), 256, SMEM_W>>>();        // pool (tensor)
        wmma_gemm<1><<<dim3(8, 8), 256, SMEM_W>>>();             // m1 (tensor)
        tile_gemm<1><<<dim3(1, NT / 32), 256>>>();               // m2 -> new h
    }
    (void)in_sizes; (void)n_in; (void)out_size;
}

// round 6
// speedup vs baseline: 3.1460x; 1.1325x over previous
#include <cuda_runtime.h>
#include <cuda_bf16.h>
#include <mma.h>
#include <stdint.h>
#include <math.h>

using namespace nvcuda;

#define NT 1024
#define HD 128
#define ED 64
#define SC 32
#define PP 32
#define B1D 512
#define B2D 1024
#define M1D 1024
#define TS 12
#define KM1 (HD + B2D)   // 1152
#define BN_INV_F 0.9999950000374997f

// ---------------- device state / scratch ----------------
static __device__ float g_h[NT * HD];
static __device__ float g_c[NT * HD];
static __device__ float g_h2[NT * HD];
static __device__ float g_lp[NT * 2];
static __device__ float g_din[NT * ED];
static __device__ float g_hpre[NT * B1D];
static __device__ float g_gates[NT * 4 * HD];
// folded scalar weights
static __device__ float g_A[B1D], g_B[B1D], g_bias1[B1D];
static __device__ float g_Wb[B1D * HD];
static __device__ float g_bias2[B2D], g_bm1[M1D], g_bm2[HD];
static __device__ float g_LW[4 * HD * 192], g_Lb[4 * HD];
// pre-tiled bf16 hi/lo weights: [nb][chunk][128r x 64k] (8192 halfwords per tile)
static __device__ __nv_bfloat16 g_W2th[8 * 8 * 8192],  g_W2tl[8 * 8 * 8192];
static __device__ __nv_bfloat16 g_M1th[8 * 18 * 8192], g_M1tl[8 * 18 * 8192];
static __device__ __nv_bfloat16 g_M2th[16 * 8192],     g_M2tl[16 * 8192];
// activation tiles (hi/lo), same [group][chunk][128x64] layout
static __device__ __nv_bfloat16 g_x1h[256 * 8 * 8192], g_x1l[256 * 8 * 8192];   // pool A
static __device__ __nv_bfloat16 g_mAh[8 * 18 * 8192],  g_mAl[8 * 18 * 8192];    // m1 A
static __device__ __nv_bfloat16 g_mBh[8 * 16 * 8192],  g_mBl[8 * 16 * 8192];    // m2 A

// ---------------- helpers ----------------
__device__ __forceinline__ uint32_t pack_bf(float v0, float v1, uint32_t* lo) {
    __nv_bfloat16 h0 = __float2bfloat16(v0), h1 = __float2bfloat16(v1);
    __nv_bfloat16 l0 = __float2bfloat16(v0 - __bfloat162float(h0));
    __nv_bfloat16 l1 = __float2bfloat16(v1 - __bfloat162float(h1));
    *lo = ((uint32_t)__bfloat16_as_ushort(l1) << 16) | __bfloat16_as_ushort(l0);
    return ((uint32_t)__bfloat16_as_ushort(h1) << 16) | __bfloat16_as_ushort(h0);
}

// ---------------- prep kernels (once per launch) ----------------
__global__ void init_state(const float* __restrict__ h0, const float* __restrict__ c0,
                           const float* __restrict__ last_pos, const float* __restrict__ last_pos_rel,
                           const float* __restrict__ embW, const float* __restrict__ embb) {
    int idx = blockIdx.x * blockDim.x + threadIdx.x;
    if (idx < NT * HD) { g_h[idx] = h0[idx]; g_c[idx] = c0[idx]; }
    if (idx < NT * 2) g_lp[idx] = last_pos[idx];
    if (idx < NT * ED) {
        int n = idx / ED, e = idx % ED;
        g_din[idx] = last_pos_rel[n * 2] * embW[e * 2] +
                     last_pos_rel[n * 2 + 1] * embW[e * 2 + 1] + embb[e];
    }
}

__global__ void fold_pp1(const float* __restrict__ pp1_W, const float* __restrict__ pp1_b,
                         const float* __restrict__ pp1_g, const float* __restrict__ pp1_be,
                         const float* __restrict__ sp_W, const float* __restrict__ sp_b) {
    int k = blockIdx.x * blockDim.x + threadIdx.x;
    if (k >= B1D) return;
    float s1 = BN_INV_F * pp1_g[k];
    const float* row = pp1_W + (size_t)k * (ED + HD);
    float sa = 0.f, sb = 0.f, sc = 0.f;
    for (int e = 0; e < ED; e++) {
        float w = row[e];
        sa += w * sp_W[e * 2]; sb += w * sp_W[e * 2 + 1]; sc += w * sp_b[e];
    }
    g_A[k] = sa * s1; g_B[k] = sb * s1;
    g_bias1[k] = (pp1_b[k] + sc) * s1 + pp1_be[k];
    for (int h = 0; h < HD; h++) g_Wb[k * HD + h] = row[ED + h] * s1;
}

__global__ void fold_LW(const float* __restrict__ Wih, const float* __restrict__ Whh,
                        const float* __restrict__ bih, const float* __restrict__ bhh) {
    for (int idx = blockIdx.x * blockDim.x + threadIdx.x; idx < 512 * 192; idx += gridDim.x * blockDim.x) {
        int r = idx / 192, cc = idx % 192;
        g_LW[idx] = (cc < 64) ? Wih[r * 64 + cc] : Whh[r * 128 + cc - 64];
        if (cc == 0) g_Lb[r] = bih[r] + bhh[r];
    }
}

// split + pre-tile weights. WM=0: W2(K=512,R=1024), 1: m1(K=1152,R=1024), 2: m2(K=1024,R=128)
template <int WM>
__global__ void prep_wB(const float* __restrict__ W, const float* __restrict__ b,
                        const float* __restrict__ g, const float* __restrict__ be) {
    constexpr int K = (WM == 0) ? B1D : (WM == 1) ? KM1 : M1D;
    constexpr int ROWS = (WM == 2) ? HD : 1024;
    constexpr int KC = K / 64;
    __nv_bfloat16* oh = (WM == 0) ? g_W2th : (WM == 1) ? g_M1th : g_M2th;
    __nv_bfloat16* ol = (WM == 0) ? g_W2tl : (WM == 1) ? g_M1tl : g_M2tl;
    float* bo = (WM == 0) ? g_bias2 : (WM == 1) ? g_bm1 : g_bm2;
    int total = ROWS * (K / 2);
    for (int p = blockIdx.x * blockDim.x + threadIdx.x; p < total; p += gridDim.x * blockDim.x) {
        int co = p / (K / 2), kp = p % (K / 2), k = kp * 2;
        int nb = co >> 7, r = co & 127, c = k >> 6, kk = k & 63;
        float s = BN_INV_F * g[co];
        float v0 = W[(size_t)co * K + k] * s, v1 = W[(size_t)co * K + k + 1] * s;
        uint32_t lo, hi = pack_bf(v0, v1, &lo);
        size_t off = ((size_t)(nb * KC + c) * 8192 + r * 64 + kk);
        *(uint32_t*)(oh + off) = hi;
        *(uint32_t*)(ol + off) = lo;
        if (kp == 0) bo[co] = b[co] * s + be[co];
    }
}

// ---------------- SIMT GEMM: MODE 0 hpre(K=128), MODE 2 gates(K=192) ----------------
template <int MODE>
__global__ __launch_bounds__(256) void tile_gemm() {
    constexpr int K = (MODE == 0) ? HD : 192;
    constexpr int LDC = (MODE == 0) ? B1D : 512;
    const float* Wp = (MODE == 0) ? g_Wb : g_LW;
    const float* bp = (MODE == 0) ? g_bias1 : g_Lb;
    float* outp = (MODE == 0) ? g_hpre : g_gates;
    int c0 = blockIdx.x * 128, grp = blockIdx.y, tid = threadIdx.x;
    int tx = tid & 31, ty = tid >> 5;
    __shared__ float a_s[32][64];
    __shared__ float w_s[64][129];
    int nbase = grp * 32;
    float acc[4][4] = {};
    for (int k0 = 0; k0 < K; k0 += 64) {
        __syncthreads();
        for (int idx = tid; idx < 32 * 64; idx += 256) {
            int j = idx >> 6, k = idx & 63, kk = k0 + k;
            float v;
            if (MODE == 0) v = g_h2[(nbase + j) * HD + kk];
            else v = (kk < 64) ? g_din[(nbase + j) * ED + kk] : g_h[(nbase + j) * HD + kk - 64];
            a_s[j][k] = v;
        }
        for (int idx = tid; idx < 128 * 64; idx += 256) {
            int c = idx >> 6, k = idx & 63;
            w_s[k][c] = Wp[(size_t)(c0 + c) * K + k0 + k];
        }
        __syncthreads();
#pragma unroll 4
        for (int k = 0; k < 64; k++) {
            float xr[4], wr[4];
#pragma unroll
            for (int jj = 0; jj < 4; jj++) xr[jj] = a_s[ty + jj * 8][k];
#pragma unroll
            for (int cc = 0; cc < 4; cc++) wr[cc] = w_s[k][tx + cc * 32];
#pragma unroll
            for (int jj = 0; jj < 4; jj++)
#pragma unroll
                for (int cc = 0; cc < 4; cc++) acc[jj][cc] = fmaf(xr[jj], wr[cc], acc[jj][cc]);
        }
    }
#pragma unroll
    for (int jj = 0; jj < 4; jj++) {
        int n = nbase + ty + jj * 8;
#pragma unroll
        for (int cc = 0; cc < 4; cc++) {
            int c = c0 + tx + cc * 32;
            outp[(size_t)n * LDC + c] = acc[jj][cc] + bp[c];
        }
    }
}

// ---------------- LSTM pointwise + h2 pack into m1 A-tiles ----------------
__global__ __launch_bounds__(128) void lstm_point(
    const float* __restrict__ posW, const float* __restrict__ posb,
    const float* __restrict__ embW, const float* __restrict__ embb,
    float* __restrict__ out_t) {
    int n = blockIdx.x, t = threadIdx.x;
    __shared__ float red0[HD], red1[HD], hs2[HD], rp[2];
    float gi = g_gates[n * 512 + 0 * HD + t];
    float gf = g_gates[n * 512 + 1 * HD + t];
    float gg = g_gates[n * 512 + 2 * HD + t];
    float go = g_gates[n * 512 + 3 * HD + t];
    float ig = 1.f / (1.f + expf(-gi));
    float fg = 1.f / (1.f + expf(-gf));
    float gv = tanhf(gg);
    float og = 1.f / (1.f + expf(-go));
    float c2 = fg * g_c[n * HD + t] + ig * gv;
    float h2 = og * tanhf(c2);
    g_c[n * HD + t] = c2;
    g_h2[n * HD + t] = h2;
    hs2[t] = h2;
    red0[t] = h2 * posW[t]; red1[t] = h2 * posW[HD + t];
    __syncthreads();
    for (int s = 64; s > 0; s >>= 1) {
        if (t < s) { red0[t] += red0[t + s]; red1[t] += red1[t + s]; }
        __syncthreads();
    }
    if (t < 2) {
        float v = ((t == 0) ? red0[0] : red1[0]) + posb[t];
        rp[t] = v;
        out_t[n * 2 + t] = v;
        g_lp[n * 2 + t] += v;
    }
    __syncthreads();
    if (t < ED) g_din[n * ED + t] = fmaf(rp[0], embW[t * 2], fmaf(rp[1], embW[t * 2 + 1], embb[t]));
    // pack h2 pairs into m1 A-tile chunks 0..1
    if (t < 64) {
        uint32_t lo;
        uint32_t hi = pack_bf(hs2[2 * t], hs2[2 * t + 1], &lo);
        int mb = n >> 7, m = n & 127;
        int c = t >> 5, kk = (t & 31) * 2;
        size_t off = (size_t)(mb * 18 + c) * 8192 + m * 64 + kk;
        *(uint32_t*)(g_mAh + off) = hi;
        *(uint32_t*)(g_mAl + off) = lo;
    }
}

// ---------------- build x1 hi/lo tiles (once per step, no nb redundancy) ----------------
__global__ __launch_bounds__(256) void build_x1() {
    int c = blockIdx.x, ib = blockIdx.y, s = blockIdx.z;
    int tid = threadIdx.x;
    __shared__ float rxs[128], rys[128];
    if (tid < 128) {
        int i = ib * 4 + (tid >> 5), j = tid & 31;
        float dx = g_lp[(s * 32 + j) * 2]     - g_lp[(s * 32 + i) * 2];
        float dy = g_lp[(s * 32 + j) * 2 + 1] - g_lp[(s * 32 + i) * 2 + 1];
        float nrm = fmaxf(sqrtf(dx * dx + dy * dy), 1e-12f);
        rxs[tid] = dx / nrm; rys[tid] = dy / nrm;
    }
    __syncthreads();
    int grp = s * 8 + ib;
    uint32_t* oh = (uint32_t*)g_x1h + (size_t)(grp * 8 + c) * 4096;
    uint32_t* ol = (uint32_t*)g_x1l + (size_t)(grp * 8 + c) * 4096;
    int kp = tid & 31, k = c * 64 + kp * 2;
    float2 ab0 = *(const float2*)(g_A + k);
    float2 bb0 = *(const float2*)(g_B + k);
#pragma unroll
    for (int q = 0; q < 16; q++) {
        int m = (tid >> 5) + q * 8;
        int pj = s * 32 + (m & 31);
        float rx = rxs[m], ry = rys[m];
        float2 hp = *(const float2*)(g_hpre + (size_t)pj * B1D + k);
        float v0 = fmaxf(hp.x + rx * ab0.x + ry * bb0.x, 0.f);
        float v1 = fmaxf(hp.y + rx * ab0.y + ry * bb0.y, 0.f);
        uint32_t lo, hi = pack_bf(v0, v1, &lo);
        oh[m * 32 + kp] = hi;
        ol[m * 32 + kp] = lo;
    }
}

// ---------------- wmma tensor GEMM (bf16 hi/lo 3-pass), copy-only staging ----------------
// GM=0: pool (KC=8, grid(8,256)), GM=1: m1 (KC=18, grid(8,8)), GM=2: m2 (KC=16, grid(1,8))
#define SMEM_W (4 * 128 * 72 * 2)

template <int GM>
__global__ __launch_bounds__(256) void wmma_gemm() {
    constexpr int KC = (GM == 0) ? 8 : (GM == 1) ? 18 : 16;
    extern __shared__ __align__(16) char smraw[];
    __nv_bfloat16* a_h = (__nv_bfloat16*)smraw;
    __nv_bfloat16* a_l = a_h + 128 * 72;
    __nv_bfloat16* w_h = a_l + 128 * 72;
    __nv_bfloat16* w_l = w_h + 128 * 72;
    float* c_s = (float*)smraw;   // epilogue reuse: 128x136 fp32 = 69632 <= 73728

    int tid = threadIdx.x, w = tid >> 5;
    int nb = blockIdx.x, grp = blockIdx.y;

    const __nv_bfloat16* Ah_g = (GM == 0) ? g_x1h : (GM == 1) ? g_mAh : g_mBh;
    const __nv_bfloat16* Al_g = (GM == 0) ? g_x1l : (GM == 1) ? g_mAl : g_mBl;
    const __nv_bfloat16* Wh_g = (GM == 0) ? g_W2th : (GM == 1) ? g_M1th : g_M2th;
    const __nv_bfloat16* Wl_g = (GM == 0) ? g_W2tl : (GM == 1) ? g_M1tl : g_M2tl;

    wmma::fragment<wmma::accumulator, 16, 16, 16, float> acc[8];
#pragma unroll
    for (int mf = 0; mf < 8; mf++) wmma::fill_fragment(acc[mf], 0.f);

    for (int c = 0; c < KC; c++) {
        __syncthreads();
        const uint4* sAh = (const uint4*)(Ah_g + (size_t)(grp * KC + c) * 8192);
        const uint4* sAl = (const uint4*)(Al_g + (size_t)(grp * KC + c) * 8192);
        const uint4* sWh = (const uint4*)(Wh_g + (size_t)(nb * KC + c) * 8192);
        const uint4* sWl = (const uint4*)(Wl_g + (size_t)(nb * KC + c) * 8192);
#pragma unroll
        for (int q = 0; q < 4; q++) {
            int idx = tid + q * 256;          // 0..1023 uint4
            int r = idx >> 3, k8 = idx & 7;
            int d = r * 72 + k8 * 8;
            *(uint4*)(a_h + d) = sAh[idx];
            *(uint4*)(a_l + d) = sAl[idx];
            *(uint4*)(w_h + d) = sWh[idx];
            *(uint4*)(w_l + d) = sWl[idx];
        }
        __syncthreads();
#pragma unroll
        for (int ks = 0; ks < 4; ks++) {
            wmma::fragment<wmma::matrix_b, 16, 16, 16, __nv_bfloat16, wmma::col_major> bh, bl;
            wmma::load_matrix_sync(bh, w_h + w * 16 * 72 + ks * 16, 72);
            wmma::load_matrix_sync(bl, w_l + w * 16 * 72 + ks * 16, 72);
#pragma unroll
            for (int mf = 0; mf < 8; mf++) {
                wmma::fragment<wmma::matrix_a, 16, 16, 16, __nv_bfloat16, wmma::row_major> ah, al;
                wmma::load_matrix_sync(ah, a_h + mf * 16 * 72 + ks * 16, 72);
                wmma::load_matrix_sync(al, a_l + mf * 16 * 72 + ks * 16, 72);
                wmma::mma_sync(acc[mf], ah, bh, acc[mf]);
                wmma::mma_sync(acc[mf], ah, bl, acc[mf]);
                wmma::mma_sync(acc[mf], al, bh, acc[mf]);
            }
        }
    }
    __syncthreads();
#pragma unroll
    for (int mf = 0; mf < 8; mf++)
        wmma::store_matrix_sync(c_s + mf * 16 * 136 + w * 16, acc[mf], 136, wmma::mem_row_major);
    __syncthreads();

    if (GM == 0) {
        // max over 32 j-rows per i, relu(+bias2), pack pairs into m1 A-tiles (chunks 2..17)
        int s = grp >> 3, ib = grp & 7;
        for (int p = tid; p < 256; p += 256) {
            int il = p >> 6, kp0 = p & 63;
            int cc0 = kp0 * 2;
            float m0 = c_s[(il * 32) * 136 + cc0];
            float m1v = c_s[(il * 32) * 136 + cc0 + 1];
#pragma unroll 8
            for (int r = 1; r < 32; r++) {
                m0  = fmaxf(m0,  c_s[(il * 32 + r) * 136 + cc0]);
                m1v = fmaxf(m1v, c_s[(il * 32 + r) * 136 + cc0 + 1]);
            }
            int col = nb * 128 + cc0;
            float v0 = fmaxf(m0 + g_bias2[col], 0.f);
            float v1 = fmaxf(m1v + g_bias2[col + 1], 0.f);
            uint32_t lo, hi = pack_bf(v0, v1, &lo);
            int ped = s * 32 + ib * 4 + il;
            int mb = ped >> 7, m = ped & 127;
            int c = 2 + nb * 2 + (kp0 >> 5), kk = cc0 & 63;
            size_t off = (size_t)(mb * 18 + c) * 8192 + m * 64 + kk;
            *(uint32_t*)(g_mAh + off) = hi;
            *(uint32_t*)(g_mAl + off) = lo;
        }
    } else if (GM == 1) {
        // relu(+bm1), pack pairs into m2 A-tiles
        for (int p = tid; p < 8192; p += 256) {
            int r = p >> 6, kp = p & 63;
            int cc0 = kp * 2, col = nb * 128 + cc0;
            float v0 = fmaxf(c_s[r * 136 + cc0]     + g_bm1[col], 0.f);
            float v1 = fmaxf(c_s[r * 136 + cc0 + 1] + g_bm1[col + 1], 0.f);
            uint32_t lo, hi = pack_bf(v0, v1, &lo);
            int c = nb * 2 + (kp >> 5), kk = cc0 & 63;
            size_t off = (size_t)(grp * 16 + c) * 8192 + r * 64 + kk;
            *(uint32_t*)(g_mBh + off) = hi;
            *(uint32_t*)(g_mBl + off) = lo;
        }
    } else {
        // m2: relu(+bm2) -> g_h fp32
        for (int p = tid; p < 16384; p += 256) {
            int r = p >> 7, cc = p & 127;
            g_h[(size_t)(grp * 128 + r) * HD + cc] = fmaxf(c_s[r * 136 + cc] + g_bm2[cc], 0.f);
        }
    }
}

// ---------------- host launch ----------------
extern "C" void kernel_launch(void* const* d_in, const int* in_sizes, int n_in,
                              void* d_out, int out_size) {
    const float* last_pos     = (const float*)d_in[0];
    const float* last_pos_rel = (const float*)d_in[1];
    const float* h0  = (const float*)d_in[2];
    const float* c0  = (const float*)d_in[3];
    const float* emb_W = (const float*)d_in[5];
    const float* emb_b = (const float*)d_in[6];
    const float* Wih = (const float*)d_in[7];
    const float* Whh = (const float*)d_in[8];
    const float* bih = (const float*)d_in[9];
    const float* bhh = (const float*)d_in[10];
    const float* pos_W = (const float*)d_in[11];
    const float* pos_b = (const float*)d_in[12];
    const float* sp_W = (const float*)d_in[13];
    const float* sp_b = (const float*)d_in[14];
    const float* pp1_W = (const float*)d_in[15];
    const float* pp1_b = (const float*)d_in[16];
    const float* pp1_g = (const float*)d_in[17];
    const float* pp1_be = (const float*)d_in[18];
    const float* pp2_W = (const float*)d_in[19];
    const float* pp2_b = (const float*)d_in[20];
    const float* pp2_g = (const float*)d_in[21];
    const float* pp2_be = (const float*)d_in[22];
    const float* m1_W = (const float*)d_in[23];
    const float* m1_b = (const float*)d_in[24];
    const float* m1_g = (const float*)d_in[25];
    const float* m1_be = (const float*)d_in[26];
    const float* m2_W = (const float*)d_in[27];
    const float* m2_b = (const float*)d_in[28];
    const float* m2_g = (const float*)d_in[29];
    const float* m2_be = (const float*)d_in[30];
    float* out = (float*)d_out;

    cudaFuncSetAttribute(wmma_gemm<0>, cudaFuncAttributeMaxDynamicSharedMemorySize, SMEM_W);
    cudaFuncSetAttribute(wmma_gemm<1>, cudaFuncAttributeMaxDynamicSharedMemorySize, SMEM_W);
    cudaFuncSetAttribute(wmma_gemm<2>, cudaFuncAttributeMaxDynamicSharedMemorySize, SMEM_W);

    init_state<<<(NT * HD + 255) / 256, 256>>>(h0, c0, last_pos, last_pos_rel, emb_W, emb_b);
    fold_pp1<<<2, 256>>>(pp1_W, pp1_b, pp1_g, pp1_be, sp_W, sp_b);
    fold_LW<<<96, 256>>>(Wih, Whh, bih, bhh);
    prep_wB<0><<<512, 256>>>(pp2_W, pp2_b, pp2_g, pp2_be);
    prep_wB<1><<<512, 256>>>(m1_W, m1_b, m1_g, m1_be);
    prep_wB<2><<<128, 256>>>(m2_W, m2_b, m2_g, m2_be);

    for (int t = 0; t < TS; t++) {
        tile_gemm<2><<<dim3(4, NT / 32), 256>>>();               // LSTM gates GEMM
        lstm_point<<<NT, 128>>>(pos_W, pos_b, emb_W, emb_b, out + (size_t)t * NT * 2);
        tile_gemm<0><<<dim3(4, NT / 32), 256>>>();               // hpre
        build_x1<<<dim3(8, 8, SC), 256>>>();                     // x1 hi/lo tiles
        wmma_gemm<0><<<dim3(8, SC * 8), 256, SMEM_W>>>();        // pool (tensor)
        wmma_gemm<1><<<dim3(8, 8), 256, SMEM_W>>>();             // m1 (tensor)
        wmma_gemm<2><<<dim3(1, 8), 256, SMEM_W>>>();             // m2 (tensor) -> new h
    }
    (void)in_sizes; (void)n_in; (void)out_size;
}

// round 7
// speedup vs baseline: 3.7487x; 1.1916x over previous
#include <cuda_runtime.h>
#include <cuda_bf16.h>
#include <mma.h>
#include <stdint.h>
#include <math.h>

using namespace nvcuda;

#define NT 1024
#define HD 128
#define ED 64
#define SC 32
#define PP 32
#define B1D 512
#define B2D 1024
#define M1D 1024
#define TS 12
#define KM1 (HD + B2D)   // 1152
#define BN_INV_F 0.9999950000374997f

// ---------------- device state / scratch ----------------
static __device__ float g_h[NT * HD];          // only h0 (t=0 gates input)
static __device__ float g_c[NT * HD];
static __device__ float g_h2[NT * HD];
static __device__ float g_lp[NT * 2];
static __device__ float g_din[NT * ED];
static __device__ float g_hpre[NT * B1D];
static __device__ float g_gates[NT * 4 * HD];
static __device__ float g_hp[4 * NT * HD];     // m2 split-K partial sums
// folded scalar weights
static __device__ float g_A[B1D], g_B[B1D], g_bias1[B1D];
static __device__ float g_Wb[B1D * HD];
static __device__ float g_bias2[B2D], g_bm1[M1D], g_bm2[HD];
static __device__ float g_LW[4 * HD * 192], g_Lb[4 * HD];
// pre-tiled bf16 hi/lo weights: [nb][chunk64][128r x 64k] (8192 halfwords / tile)
static __device__ __nv_bfloat16 g_W2th[8 * 8 * 8192],  g_W2tl[8 * 8 * 8192];
static __device__ __nv_bfloat16 g_M1th[8 * 18 * 8192], g_M1tl[8 * 18 * 8192];
static __device__ __nv_bfloat16 g_M2th[16 * 8192],     g_M2tl[16 * 8192];
// activation tiles (hi/lo), same [group][chunk64][128x64] layout
static __device__ __nv_bfloat16 g_x1h[256 * 8 * 8192], g_x1l[256 * 8 * 8192];   // pool A
static __device__ __nv_bfloat16 g_mAh[8 * 18 * 8192],  g_mAl[8 * 18 * 8192];    // m1 A
static __device__ __nv_bfloat16 g_mBh[8 * 16 * 8192],  g_mBl[8 * 16 * 8192];    // m2 A

// ---------------- helpers ----------------
__device__ __forceinline__ uint32_t pack_bf(float v0, float v1, uint32_t* lo) {
    __nv_bfloat16 h0 = __float2bfloat16(v0), h1 = __float2bfloat16(v1);
    __nv_bfloat16 l0 = __float2bfloat16(v0 - __bfloat162float(h0));
    __nv_bfloat16 l1 = __float2bfloat16(v1 - __bfloat162float(h1));
    *lo = ((uint32_t)__bfloat16_as_ushort(l1) << 16) | __bfloat16_as_ushort(l0);
    return ((uint32_t)__bfloat16_as_ushort(h1) << 16) | __bfloat16_as_ushort(h0);
}
__device__ __forceinline__ uint32_t smem_u32(const void* p) {
    uint32_t a;
    asm("{ .reg .u64 t; cvta.to.shared.u64 t, %1; cvt.u32.u64 %0, t; }" : "=r"(a) : "l"(p));
    return a;
}
__device__ __forceinline__ void cpa(uint32_t dsmem, const void* gsrc) {
    asm volatile("cp.async.cg.shared.global [%0], [%1], 16;" :: "r"(dsmem), "l"(gsrc) : "memory");
}
#define CPA_COMMIT() asm volatile("cp.async.commit_group;" ::: "memory")
#define CPA_WAIT1()  asm volatile("cp.async.wait_group 1;" ::: "memory")
#define CPA_WAIT0()  asm volatile("cp.async.wait_group 0;" ::: "memory")

// ---------------- prep kernels (once per launch) ----------------
__global__ void init_state(const float* __restrict__ h0, const float* __restrict__ c0,
                           const float* __restrict__ last_pos, const float* __restrict__ last_pos_rel,
                           const float* __restrict__ embW, const float* __restrict__ embb) {
    int idx = blockIdx.x * blockDim.x + threadIdx.x;
    if (idx < NT * HD) { g_h[idx] = h0[idx]; g_c[idx] = c0[idx]; }
    if (idx < NT * 2) g_lp[idx] = last_pos[idx];
    if (idx < NT * ED) {
        int n = idx / ED, e = idx % ED;
        g_din[idx] = last_pos_rel[n * 2] * embW[e * 2] +
                     last_pos_rel[n * 2 + 1] * embW[e * 2 + 1] + embb[e];
    }
}

__global__ void fold_pp1(const float* __restrict__ pp1_W, const float* __restrict__ pp1_b,
                         const float* __restrict__ pp1_g, const float* __restrict__ pp1_be,
                         const float* __restrict__ sp_W, const float* __restrict__ sp_b) {
    int k = blockIdx.x * blockDim.x + threadIdx.x;
    if (k >= B1D) return;
    float s1 = BN_INV_F * pp1_g[k];
    const float* row = pp1_W + (size_t)k * (ED + HD);
    float sa = 0.f, sb = 0.f, sc = 0.f;
    for (int e = 0; e < ED; e++) {
        float w = row[e];
        sa += w * sp_W[e * 2]; sb += w * sp_W[e * 2 + 1]; sc += w * sp_b[e];
    }
    g_A[k] = sa * s1; g_B[k] = sb * s1;
    g_bias1[k] = (pp1_b[k] + sc) * s1 + pp1_be[k];
    for (int h = 0; h < HD; h++) g_Wb[k * HD + h] = row[ED + h] * s1;
}

__global__ void fold_LW(const float* __restrict__ Wih, const float* __restrict__ Whh,
                        const float* __restrict__ bih, const float* __restrict__ bhh) {
    for (int idx = blockIdx.x * blockDim.x + threadIdx.x; idx < 512 * 192; idx += gridDim.x * blockDim.x) {
        int r = idx / 192, cc = idx % 192;
        g_LW[idx] = (cc < 64) ? Wih[r * 64 + cc] : Whh[r * 128 + cc - 64];
        if (cc == 0) g_Lb[r] = bih[r] + bhh[r];
    }
}

// split + pre-tile weights. WM=0: W2(K=512,R=1024), 1: m1(K=1152,R=1024), 2: m2(K=1024,R=128)
template <int WM>
__global__ void prep_wB(const float* __restrict__ W, const float* __restrict__ b,
                        const float* __restrict__ g, const float* __restrict__ be) {
    constexpr int K = (WM == 0) ? B1D : (WM == 1) ? KM1 : M1D;
    constexpr int ROWS = (WM == 2) ? HD : 1024;
    constexpr int KC = K / 64;
    __nv_bfloat16* oh = (WM == 0) ? g_W2th : (WM == 1) ? g_M1th : g_M2th;
    __nv_bfloat16* ol = (WM == 0) ? g_W2tl : (WM == 1) ? g_M1tl : g_M2tl;
    float* bo = (WM == 0) ? g_bias2 : (WM == 1) ? g_bm1 : g_bm2;
    int total = ROWS * (K / 2);
    for (int p = blockIdx.x * blockDim.x + threadIdx.x; p < total; p += gridDim.x * blockDim.x) {
        int co = p / (K / 2), kp = p % (K / 2), k = kp * 2;
        int nb = co >> 7, r = co & 127, c = k >> 6, kk = k & 63;
        float s = BN_INV_F * g[co];
        float v0 = W[(size_t)co * K + k] * s, v1 = W[(size_t)co * K + k + 1] * s;
        uint32_t lo, hi = pack_bf(v0, v1, &lo);
        size_t off = ((size_t)(nb * KC + c) * 8192 + r * 64 + kk);
        *(uint32_t*)(oh + off) = hi;
        *(uint32_t*)(ol + off) = lo;
        if (kp == 0) bo[co] = b[co] * s + be[co];
    }
}

// ---------------- SIMT GEMM: MODE 0 hpre(K=128), MODE 2 gates(K=192) ----------------
template <int MODE, int FIRST>
__global__ __launch_bounds__(256) void tile_gemm() {
    constexpr int K = (MODE == 0) ? HD : 192;
    constexpr int LDC = (MODE == 0) ? B1D : 512;
    const float* Wp = (MODE == 0) ? g_Wb : g_LW;
    const float* bp = (MODE == 0) ? g_bias1 : g_Lb;
    float* outp = (MODE == 0) ? g_hpre : g_gates;
    int c0 = blockIdx.x * 128, grp = blockIdx.y, tid = threadIdx.x;
    int tx = tid & 31, ty = tid >> 5;
    __shared__ float a_s[32][64];
    __shared__ float w_s[64][129];
    int nbase = grp * 32;
    float acc[4][4] = {};
    for (int k0 = 0; k0 < K; k0 += 64) {
        __syncthreads();
        for (int idx = tid; idx < 32 * 64; idx += 256) {
            int j = idx >> 6, k = idx & 63, kk = k0 + k;
            float v;
            if (MODE == 0) v = g_h2[(nbase + j) * HD + kk];
            else if (kk < 64) v = g_din[(nbase + j) * ED + kk];
            else {
                int ped = nbase + j, cc = kk - 64;
                if (FIRST) v = g_h[ped * HD + cc];
                else {
                    float sum = g_hp[(size_t)ped * HD + cc]
                              + g_hp[(size_t)(NT + ped) * HD + cc]
                              + g_hp[(size_t)(2 * NT + ped) * HD + cc]
                              + g_hp[(size_t)(3 * NT + ped) * HD + cc];
                    v = fmaxf(sum + g_bm2[cc], 0.f);
                }
            }
            a_s[j][k] = v;
        }
        for (int idx = tid; idx < 128 * 64; idx += 256) {
            int c = idx >> 6, k = idx & 63;
            w_s[k][c] = Wp[(size_t)(c0 + c) * K + k0 + k];
        }
        __syncthreads();
#pragma unroll 4
        for (int k = 0; k < 64; k++) {
            float xr[4], wr[4];
#pragma unroll
            for (int jj = 0; jj < 4; jj++) xr[jj] = a_s[ty + jj * 8][k];
#pragma unroll
            for (int cc = 0; cc < 4; cc++) wr[cc] = w_s[k][tx + cc * 32];
#pragma unroll
            for (int jj = 0; jj < 4; jj++)
#pragma unroll
                for (int cc = 0; cc < 4; cc++) acc[jj][cc] = fmaf(xr[jj], wr[cc], acc[jj][cc]);
        }
    }
#pragma unroll
    for (int jj = 0; jj < 4; jj++) {
        int n = nbase + ty + jj * 8;
#pragma unroll
        for (int cc = 0; cc < 4; cc++) {
            int c = c0 + tx + cc * 32;
            outp[(size_t)n * LDC + c] = acc[jj][cc] + bp[c];
        }
    }
}

// ---------------- LSTM pointwise + h2 pack into m1 A-tiles ----------------
__global__ __launch_bounds__(128) void lstm_point(
    const float* __restrict__ posW, const float* __restrict__ posb,
    const float* __restrict__ embW, const float* __restrict__ embb,
    float* __restrict__ out_t) {
    int n = blockIdx.x, t = threadIdx.x;
    __shared__ float red0[HD], red1[HD], hs2[HD], rp[2];
    float gi = g_gates[n * 512 + 0 * HD + t];
    float gf = g_gates[n * 512 + 1 * HD + t];
    float gg = g_gates[n * 512 + 2 * HD + t];
    float go = g_gates[n * 512 + 3 * HD + t];
    float ig = 1.f / (1.f + expf(-gi));
    float fg = 1.f / (1.f + expf(-gf));
    float gv = tanhf(gg);
    float og = 1.f / (1.f + expf(-go));
    float c2 = fg * g_c[n * HD + t] + ig * gv;
    float h2 = og * tanhf(c2);
    g_c[n * HD + t] = c2;
    g_h2[n * HD + t] = h2;
    hs2[t] = h2;
    red0[t] = h2 * posW[t]; red1[t] = h2 * posW[HD + t];
    __syncthreads();
    for (int s = 64; s > 0; s >>= 1) {
        if (t < s) { red0[t] += red0[t + s]; red1[t] += red1[t + s]; }
        __syncthreads();
    }
    if (t < 2) {
        float v = ((t == 0) ? red0[0] : red1[0]) + posb[t];
        rp[t] = v;
        out_t[n * 2 + t] = v;
        g_lp[n * 2 + t] += v;
    }
    __syncthreads();
    if (t < ED) g_din[n * ED + t] = fmaf(rp[0], embW[t * 2], fmaf(rp[1], embW[t * 2 + 1], embb[t]));
    if (t < 64) {
        uint32_t lo;
        uint32_t hi = pack_bf(hs2[2 * t], hs2[2 * t + 1], &lo);
        int mb = n >> 7, m = n & 127;
        int c = t >> 5, kk = (t & 31) * 2;
        size_t off = (size_t)(mb * 18 + c) * 8192 + m * 64 + kk;
        *(uint32_t*)(g_mAh + off) = hi;
        *(uint32_t*)(g_mAl + off) = lo;
    }
}

// ---------------- build x1 hi/lo tiles (once per step) ----------------
__global__ __launch_bounds__(256) void build_x1() {
    int c = blockIdx.x, ib = blockIdx.y, s = blockIdx.z;
    int tid = threadIdx.x;
    __shared__ float rxs[128], rys[128];
    if (tid < 128) {
        int i = ib * 4 + (tid >> 5), j = tid & 31;
        float dx = g_lp[(s * 32 + j) * 2]     - g_lp[(s * 32 + i) * 2];
        float dy = g_lp[(s * 32 + j) * 2 + 1] - g_lp[(s * 32 + i) * 2 + 1];
        float nrm = fmaxf(sqrtf(dx * dx + dy * dy), 1e-12f);
        rxs[tid] = dx / nrm; rys[tid] = dy / nrm;
    }
    __syncthreads();
    int grp = s * 8 + ib;
    uint32_t* oh = (uint32_t*)g_x1h + (size_t)(grp * 8 + c) * 4096;
    uint32_t* ol = (uint32_t*)g_x1l + (size_t)(grp * 8 + c) * 4096;
    int kp = tid & 31, k = c * 64 + kp * 2;
    float2 ab0 = *(const float2*)(g_A + k);
    float2 bb0 = *(const float2*)(g_B + k);
#pragma unroll
    for (int q = 0; q < 16; q++) {
        int m = (tid >> 5) + q * 8;
        int pj = s * 32 + (m & 31);
        float rx = rxs[m], ry = rys[m];
        float2 hp = *(const float2*)(g_hpre + (size_t)pj * B1D + k);
        float v0 = fmaxf(hp.x + rx * ab0.x + ry * bb0.x, 0.f);
        float v1 = fmaxf(hp.y + rx * ab0.y + ry * bb0.y, 0.f);
        uint32_t lo, hi = pack_bf(v0, v1, &lo);
        oh[m * 32 + kp] = hi;
        ol[m * 32 + kp] = lo;
    }
}

// ---------------- wmma tensor GEMM with cp.async 2-stage pipeline ----------------
// smem stage: [a_h | a_l | w_h | w_l], each 128x40 bf16 (10240 B); 2 stages = 81920 B.
// GM=0: pool, grid(8 nb, 256 grp), KC=16 (k=32 sub-chunks), MF=8.
// GM=1: m1,   grid(8 nb, 16 mrow), KC=36, MF=4 (64 rows).
// GM=2: m2,   grid(4 kslice, 8 mb), KC=8 per slice, MF=8, partials to g_hp.
#define SMEM_W 81920

template <int GM>
__global__ __launch_bounds__(256) void wmma_gemm() {
    constexpr int KC = (GM == 0) ? 16 : (GM == 1) ? 36 : 8;
    constexpr int MF = (GM == 1) ? 4 : 8;
    constexpr int ROWS = MF * 16;
    extern __shared__ __align__(16) char smraw[];
    uint32_t base = smem_u32(smraw);
    float* c_s = (float*)smraw;

    int tid = threadIdx.x, w = tid >> 5;
    int nbX = blockIdx.x, grpY = blockIdx.y;

    const __nv_bfloat16* Ah_g = (GM == 0) ? g_x1h : (GM == 1) ? g_mAh : g_mBh;
    const __nv_bfloat16* Al_g = (GM == 0) ? g_x1l : (GM == 1) ? g_mAl : g_mBl;
    const __nv_bfloat16* Wh_g = (GM == 0) ? g_W2th : (GM == 1) ? g_M1th : g_M2th;
    const __nv_bfloat16* Wl_g = (GM == 0) ? g_W2tl : (GM == 1) ? g_M1tl : g_M2tl;

    auto stage = [&](int buf, int c) {
        int tile, sub, roff, wtile;
        if (GM == 0) { tile = grpY * 8 + (c >> 1); sub = c & 1; roff = 0; wtile = nbX * 8 + (c >> 1); }
        else if (GM == 1) { tile = (grpY >> 1) * 18 + (c >> 1); sub = c & 1; roff = (grpY & 1) * 64; wtile = nbX * 18 + (c >> 1); }
        else { int gch = nbX * 8 + c; tile = grpY * 16 + (gch >> 1); sub = gch & 1; roff = 0; wtile = gch >> 1; }
        uint32_t sb = base + buf * 40960;
        for (int i = tid; i < ROWS * 4; i += 256) {
            int r = i >> 2, seg = i & 3;
            size_t so = (size_t)tile * 8192 + (roff + r) * 64 + sub * 32 + seg * 8;
            uint32_t d = sb + r * 80 + seg * 16;
            cpa(d, Ah_g + so);
            cpa(d + 10240, Al_g + so);
        }
        for (int i = tid; i < 512; i += 256) {
            int r = i >> 2, seg = i & 3;
            size_t so = (size_t)wtile * 8192 + r * 64 + sub * 32 + seg * 8;
            uint32_t d = sb + 20480 + r * 80 + seg * 16;
            cpa(d, Wh_g + so);
            cpa(d + 10240, Wl_g + so);
        }
        CPA_COMMIT();
    };

    wmma::fragment<wmma::accumulator, 16, 16, 16, float> acc[MF];
#pragma unroll
    for (int mf = 0; mf < MF; mf++) wmma::fill_fragment(acc[mf], 0.f);

    stage(0, 0);
    for (int c = 0; c < KC; c++) {
        if (c + 1 < KC) stage((c + 1) & 1, c + 1);
        if (c + 1 < KC) { CPA_WAIT1(); } else { CPA_WAIT0(); }
        __syncthreads();
        const __nv_bfloat16* a_h = (const __nv_bfloat16*)(smraw + (c & 1) * 40960);
        const __nv_bfloat16* a_l = a_h + 5120;
        const __nv_bfloat16* w_h = a_h + 10240;
        const __nv_bfloat16* w_l = a_h + 15360;
#pragma unroll
        for (int ks = 0; ks < 2; ks++) {
            wmma::fragment<wmma::matrix_b, 16, 16, 16, __nv_bfloat16, wmma::col_major> bh, bl;
            wmma::load_matrix_sync(bh, w_h + w * 16 * 40 + ks * 16, 40);
            wmma::load_matrix_sync(bl, w_l + w * 16 * 40 + ks * 16, 40);
#pragma unroll
            for (int mf = 0; mf < MF; mf++) {
                wmma::fragment<wmma::matrix_a, 16, 16, 16, __nv_bfloat16, wmma::row_major> ah, al;
                wmma::load_matrix_sync(ah, a_h + mf * 16 * 40 + ks * 16, 40);
                wmma::load_matrix_sync(al, a_l + mf * 16 * 40 + ks * 16, 40);
                wmma::mma_sync(acc[mf], ah, bh, acc[mf]);
                wmma::mma_sync(acc[mf], ah, bl, acc[mf]);
                wmma::mma_sync(acc[mf], al, bh, acc[mf]);
            }
        }
        __syncthreads();
    }

#pragma unroll
    for (int mf = 0; mf < MF; mf++)
        wmma::store_matrix_sync(c_s + mf * 16 * 136 + w * 16, acc[mf], 136, wmma::mem_row_major);
    __syncthreads();

    if (GM == 0) {
        // max over 32 j-rows per i, relu(+bias2), pack pairs into m1 A-tiles (chunks 2..17)
        int s = grpY >> 3, ib = grpY & 7;
        for (int p = tid; p < 256; p += 256) {
            int il = p >> 6, kp0 = p & 63;
            int cc0 = kp0 * 2;
            float m0 = c_s[(il * 32) * 136 + cc0];
            float m1v = c_s[(il * 32) * 136 + cc0 + 1];
#pragma unroll 8
            for (int r = 1; r < 32; r++) {
                m0  = fmaxf(m0,  c_s[(il * 32 + r) * 136 + cc0]);
                m1v = fmaxf(m1v, c_s[(il * 32 + r) * 136 + cc0 + 1]);
            }
            int col = nbX * 128 + cc0;
            float v0 = fmaxf(m0 + g_bias2[col], 0.f);
            float v1 = fmaxf(m1v + g_bias2[col + 1], 0.f);
            uint32_t lo, hi = pack_bf(v0, v1, &lo);
            int ped = s * 32 + ib * 4 + il;
            int mb = ped >> 7, m = ped & 127;
            int c = 2 + nbX * 2 + (kp0 >> 5), kk = cc0 & 63;
            size_t off = (size_t)(mb * 18 + c) * 8192 + m * 64 + kk;
            *(uint32_t*)(g_mAh + off) = hi;
            *(uint32_t*)(g_mAl + off) = lo;
        }
    } else if (GM == 1) {
        // relu(+bm1), pack pairs into m2 A-tiles (64 rows)
        for (int p = tid; p < 4096; p += 256) {
            int r = p >> 6, kp = p & 63;
            int cc0 = kp * 2, col = nbX * 128 + cc0;
            float v0 = fmaxf(c_s[r * 136 + cc0]     + g_bm1[col], 0.f);
            float v1 = fmaxf(c_s[r * 136 + cc0 + 1] + g_bm1[col + 1], 0.f);
            uint32_t lo, hi = pack_bf(v0, v1, &lo);
            int ped = grpY * 64 + r;
            int mb = ped >> 7, m = ped & 127;
            int c = nbX * 2 + (kp >> 5), kk = cc0 & 63;
            size_t off = (size_t)(mb * 16 + c) * 8192 + m * 64 + kk;
            *(uint32_t*)(g_mBh + off) = hi;
            *(uint32_t*)(g_mBl + off) = lo;
        }
    } else {
        // m2 partial (no bias/relu) -> g_hp[kslice]
        float* dst = g_hp + (size_t)nbX * NT * HD + (size_t)grpY * 128 * HD;
        for (int p = tid; p < 16384; p += 256) {
            int r = p >> 7, cc = p & 127;
            dst[r * HD + cc] = c_s[r * 136 + cc];
        }
    }
}

// ---------------- host launch ----------------
extern "C" void kernel_launch(void* const* d_in, const int* in_sizes, int n_in,
                              void* d_out, int out_size) {
    const float* last_pos     = (const float*)d_in[0];
    const float* last_pos_rel = (const float*)d_in[1];
    const float* h0  = (const float*)d_in[2];
    const float* c0  = (const float*)d_in[3];
    const float* emb_W = (const float*)d_in[5];
    const float* emb_b = (const float*)d_in[6];
    const float* Wih = (const float*)d_in[7];
    const float* Whh = (const float*)d_in[8];
    const float* bih = (const float*)d_in[9];
    const float* bhh = (const float*)d_in[10];
    const float* pos_W = (const float*)d_in[11];
    const float* pos_b = (const float*)d_in[12];
    const float* sp_W = (const float*)d_in[13];
    const float* sp_b = (const float*)d_in[14];
    const float* pp1_W = (const float*)d_in[15];
    const float* pp1_b = (const float*)d_in[16];
    const float* pp1_g = (const float*)d_in[17];
    const float* pp1_be = (const float*)d_in[18];
    const float* pp2_W = (const float*)d_in[19];
    const float* pp2_b = (const float*)d_in[20];
    const float* pp2_g = (const float*)d_in[21];
    const float* pp2_be = (const float*)d_in[22];
    const float* m1_W = (const float*)d_in[23];
    const float* m1_b = (const float*)d_in[24];
    const float* m1_g = (const float*)d_in[25];
    const float* m1_be = (const float*)d_in[26];
    const float* m2_W = (const float*)d_in[27];
    const float* m2_b = (const float*)d_in[28];
    const float* m2_g = (const float*)d_in[29];
    const float* m2_be = (const float*)d_in[30];
    float* out = (float*)d_out;

    cudaFuncSetAttribute(wmma_gemm<0>, cudaFuncAttributeMaxDynamicSharedMemorySize, SMEM_W);
    cudaFuncSetAttribute(wmma_gemm<1>, cudaFuncAttributeMaxDynamicSharedMemorySize, SMEM_W);
    cudaFuncSetAttribute(wmma_gemm<2>, cudaFuncAttributeMaxDynamicSharedMemorySize, SMEM_W);

    init_state<<<(NT * HD + 255) / 256, 256>>>(h0, c0, last_pos, last_pos_rel, emb_W, emb_b);
    fold_pp1<<<2, 256>>>(pp1_W, pp1_b, pp1_g, pp1_be, sp_W, sp_b);
    fold_LW<<<96, 256>>>(Wih, Whh, bih, bhh);
    prep_wB<0><<<512, 256>>>(pp2_W, pp2_b, pp2_g, pp2_be);
    prep_wB<1><<<512, 256>>>(m1_W, m1_b, m1_g, m1_be);
    prep_wB<2><<<128, 256>>>(m2_W, m2_b, m2_g, m2_be);

    for (int t = 0; t < TS; t++) {
        if (t == 0) tile_gemm<2, 1><<<dim3(4, NT / 32), 256>>>();  // gates (h from h0)
        else        tile_gemm<2, 0><<<dim3(4, NT / 32), 256>>>();  // gates (h = relu(sum hp + bm2))
        lstm_point<<<NT, 128>>>(pos_W, pos_b, emb_W, emb_b, out + (size_t)t * NT * 2);
        tile_gemm<0, 0><<<dim3(4, NT / 32), 256>>>();              // hpre
        build_x1<<<dim3(8, 8, SC), 256>>>();                       // x1 hi/lo tiles
        wmma_gemm<0><<<dim3(8, SC * 8), 256, SMEM_W>>>();          // pool (tensor, pipelined)
        wmma_gemm<1><<<dim3(8, 16), 256, SMEM_W>>>();              // m1 (tensor, pipelined)
        wmma_gemm<2><<<dim3(4, 8), 256, SMEM_W>>>();               // m2 split-K partials
    }
    (void)in_sizes; (void)n_in; (void)out_size;
}

// round 8
// speedup vs baseline: 5.8352x; 1.5566x over previous
#include <cuda_runtime.h>
#include <cuda_fp16.h>
#include <mma.h>
#include <stdint.h>
#include <math.h>

using namespace nvcuda;

#define NT 1024
#define HD 128
#define ED 64
#define SC 32
#define PP 32
#define B1D 512
#define B2D 1024
#define M1D 1024
#define TS 12
#define KM1 (HD + B2D)   // 1152
#define BN_INV_F 0.9999950000374997f

// ---------------- device state / scratch ----------------
static __device__ float g_h[NT * HD];
static __device__ float g_c[NT * HD];
static __device__ float g_h2[NT * HD];
static __device__ float g_lp[NT * 2];
static __device__ float g_din[NT * ED];
static __device__ float g_hpre[NT * B1D];
static __device__ float g_gates[NT * 4 * HD];
static __device__ float g_hp[4 * NT * HD];     // m2 split-K partials
// folded scalar weights
static __device__ float g_A[B1D], g_B[B1D], g_bias1[B1D];
static __device__ float g_Wb[B1D * HD];
static __device__ float g_bias2[B2D], g_bm1[M1D], g_bm2[HD];
static __device__ float g_LW[4 * HD * 192], g_Lb[4 * HD];
// pre-tiled fp16 hi/lo weights: [nb][chunk64][128r x 64k] tiles (8192 halfs)
static __device__ __half g_W2th[8 * 8 * 8192],  g_W2tl[8 * 8 * 8192];
static __device__ __half g_M1th[8 * 18 * 8192], g_M1tl[8 * 18 * 8192];
static __device__ __half g_M2th[16 * 8192],     g_M2tl[16 * 8192];
// activation tiles, fp16 single (hi only), [group][chunk64][128x64]
static __device__ __half g_x1h[256 * 8 * 8192];   // pool A
static __device__ __half g_mAh[8 * 18 * 8192];    // m1 A
static __device__ __half g_mBh[8 * 16 * 8192];    // m2 A

// ---------------- helpers ----------------
__device__ __forceinline__ uint32_t pack2hf(float v0, float v1) {
    __half2 h = __floats2half2_rn(v0, v1);
    return *(uint32_t*)&h;
}
__device__ __forceinline__ uint32_t smem_u32(const void* p) {
    uint32_t a;
    asm("{ .reg .u64 t; cvta.to.shared.u64 t, %1; cvt.u32.u64 %0, t; }" : "=r"(a) : "l"(p));
    return a;
}
__device__ __forceinline__ void cpa(uint32_t dsmem, const void* gsrc) {
    asm volatile("cp.async.cg.shared.global [%0], [%1], 16;" :: "r"(dsmem), "l"(gsrc) : "memory");
}
#define CPA_COMMIT() asm volatile("cp.async.commit_group;" ::: "memory")
#define CPA_WAIT1()  asm volatile("cp.async.wait_group 1;" ::: "memory")
#define CPA_WAIT0()  asm volatile("cp.async.wait_group 0;" ::: "memory")

// ---------------- prep kernels (once per launch) ----------------
__global__ void init_state(const float* __restrict__ h0, const float* __restrict__ c0,
                           const float* __restrict__ last_pos, const float* __restrict__ last_pos_rel,
                           const float* __restrict__ embW, const float* __restrict__ embb) {
    int idx = blockIdx.x * blockDim.x + threadIdx.x;
    if (idx < NT * HD) { g_h[idx] = h0[idx]; g_c[idx] = c0[idx]; }
    if (idx < NT * 2) g_lp[idx] = last_pos[idx];
    if (idx < NT * ED) {
        int n = idx / ED, e = idx % ED;
        g_din[idx] = last_pos_rel[n * 2] * embW[e * 2] +
                     last_pos_rel[n * 2 + 1] * embW[e * 2 + 1] + embb[e];
    }
}

__global__ void fold_pp1(const float* __restrict__ pp1_W, const float* __restrict__ pp1_b,
                         const float* __restrict__ pp1_g, const float* __restrict__ pp1_be,
                         const float* __restrict__ sp_W, const float* __restrict__ sp_b) {
    int k = blockIdx.x * blockDim.x + threadIdx.x;
    if (k >= B1D) return;
    float s1 = BN_INV_F * pp1_g[k];
    const float* row = pp1_W + (size_t)k * (ED + HD);
    float sa = 0.f, sb = 0.f, sc = 0.f;
    for (int e = 0; e < ED; e++) {
        float w = row[e];
        sa += w * sp_W[e * 2]; sb += w * sp_W[e * 2 + 1]; sc += w * sp_b[e];
    }
    g_A[k] = sa * s1; g_B[k] = sb * s1;
    g_bias1[k] = (pp1_b[k] + sc) * s1 + pp1_be[k];
    for (int h = 0; h < HD; h++) g_Wb[k * HD + h] = row[ED + h] * s1;
}

__global__ void fold_LW(const float* __restrict__ Wih, const float* __restrict__ Whh,
                        const float* __restrict__ bih, const float* __restrict__ bhh) {
    for (int idx = blockIdx.x * blockDim.x + threadIdx.x; idx < 512 * 192; idx += gridDim.x * blockDim.x) {
        int r = idx / 192, cc = idx % 192;
        g_LW[idx] = (cc < 64) ? Wih[r * 64 + cc] : Whh[r * 128 + cc - 64];
        if (cc == 0) g_Lb[r] = bih[r] + bhh[r];
    }
}

// split + pre-tile weights (fp16 hi/lo). WM=0: W2(K=512), 1: m1(K=1152), 2: m2(K=1024,R=128)
template <int WM>
__global__ void prep_wB(const float* __restrict__ W, const float* __restrict__ b,
                        const float* __restrict__ g, const float* __restrict__ be) {
    constexpr int K = (WM == 0) ? B1D : (WM == 1) ? KM1 : M1D;
    constexpr int ROWS = (WM == 2) ? HD : 1024;
    constexpr int KC = K / 64;
    __half* oh = (WM == 0) ? g_W2th : (WM == 1) ? g_M1th : g_M2th;
    __half* ol = (WM == 0) ? g_W2tl : (WM == 1) ? g_M1tl : g_M2tl;
    float* bo = (WM == 0) ? g_bias2 : (WM == 1) ? g_bm1 : g_bm2;
    int total = ROWS * (K / 2);
    for (int p = blockIdx.x * blockDim.x + threadIdx.x; p < total; p += gridDim.x * blockDim.x) {
        int co = p / (K / 2), kp = p % (K / 2), k = kp * 2;
        int nb = co >> 7, r = co & 127, c = k >> 6;
        float s = BN_INV_F * g[co];
        float v0 = W[(size_t)co * K + k] * s, v1 = W[(size_t)co * K + k + 1] * s;
        __half h0 = __float2half_rn(v0), h1 = __float2half_rn(v1);
        __half l0 = __float2half_rn(v0 - __half2float(h0));
        __half l1 = __float2half_rn(v1 - __half2float(h1));
        size_t woff = (size_t)(nb * KC + c) * 4096 + r * 32 + (kp & 31);
        ((uint32_t*)oh)[woff] = ((uint32_t)__half_as_ushort(h1) << 16) | __half_as_ushort(h0);
        ((uint32_t*)ol)[woff] = ((uint32_t)__half_as_ushort(l1) << 16) | __half_as_ushort(l0);
        if (kp == 0) bo[co] = b[co] * s + be[co];
    }
}

// ---------------- SIMT GEMM: MODE 0 hpre(K=128), MODE 2 gates(K=192) ----------------
template <int MODE, int FIRST>
__global__ __launch_bounds__(256) void tile_gemm() {
    constexpr int K = (MODE == 0) ? HD : 192;
    constexpr int LDC = (MODE == 0) ? B1D : 512;
    const float* Wp = (MODE == 0) ? g_Wb : g_LW;
    const float* bp = (MODE == 0) ? g_bias1 : g_Lb;
    float* outp = (MODE == 0) ? g_hpre : g_gates;
    int c0 = blockIdx.x * 128, grp = blockIdx.y, tid = threadIdx.x;
    int tx = tid & 31, ty = tid >> 5;
    __shared__ float a_s[32][64];
    __shared__ float w_s[64][129];
    int nbase = grp * 32;
    float acc[4][4] = {};
    for (int k0 = 0; k0 < K; k0 += 64) {
        __syncthreads();
        for (int idx = tid; idx < 32 * 64; idx += 256) {
            int j = idx >> 6, k = idx & 63, kk = k0 + k;
            float v;
            if (MODE == 0) v = g_h2[(nbase + j) * HD + kk];
            else if (kk < 64) v = g_din[(nbase + j) * ED + kk];
            else {
                int ped = nbase + j, cc = kk - 64;
                if (FIRST) v = g_h[ped * HD + cc];
                else {
                    float sum = g_hp[(size_t)ped * HD + cc]
                              + g_hp[(size_t)(NT + ped) * HD + cc]
                              + g_hp[(size_t)(2 * NT + ped) * HD + cc]
                              + g_hp[(size_t)(3 * NT + ped) * HD + cc];
                    v = fmaxf(sum + g_bm2[cc], 0.f);
                }
            }
            a_s[j][k] = v;
        }
        for (int idx = tid; idx < 128 * 64; idx += 256) {
            int c = idx >> 6, k = idx & 63;
            w_s[k][c] = Wp[(size_t)(c0 + c) * K + k0 + k];
        }
        __syncthreads();
#pragma unroll 4
        for (int k = 0; k < 64; k++) {
            float xr[4], wr[4];
#pragma unroll
            for (int jj = 0; jj < 4; jj++) xr[jj] = a_s[ty + jj * 8][k];
#pragma unroll
            for (int cc = 0; cc < 4; cc++) wr[cc] = w_s[k][tx + cc * 32];
#pragma unroll
            for (int jj = 0; jj < 4; jj++)
#pragma unroll
                for (int cc = 0; cc < 4; cc++) acc[jj][cc] = fmaf(xr[jj], wr[cc], acc[jj][cc]);
        }
    }
#pragma unroll
    for (int jj = 0; jj < 4; jj++) {
        int n = nbase + ty + jj * 8;
#pragma unroll
        for (int cc = 0; cc < 4; cc++) {
            int c = c0 + tx + cc * 32;
            outp[(size_t)n * LDC + c] = acc[jj][cc] + bp[c];
        }
    }
}

// ---------------- LSTM pointwise + h2 pack into m1 A-tiles ----------------
__global__ __launch_bounds__(128) void lstm_point(
    const float* __restrict__ posW, const float* __restrict__ posb,
    const float* __restrict__ embW, const float* __restrict__ embb,
    float* __restrict__ out_t) {
    int n = blockIdx.x, t = threadIdx.x;
    __shared__ float red0[HD], red1[HD], hs2[HD], rp[2];
    float gi = g_gates[n * 512 + 0 * HD + t];
    float gf = g_gates[n * 512 + 1 * HD + t];
    float gg = g_gates[n * 512 + 2 * HD + t];
    float go = g_gates[n * 512 + 3 * HD + t];
    float ig = 1.f / (1.f + expf(-gi));
    float fg = 1.f / (1.f + expf(-gf));
    float gv = tanhf(gg);
    float og = 1.f / (1.f + expf(-go));
    float c2 = fg * g_c[n * HD + t] + ig * gv;
    float h2 = og * tanhf(c2);
    g_c[n * HD + t] = c2;
    g_h2[n * HD + t] = h2;
    hs2[t] = h2;
    red0[t] = h2 * posW[t]; red1[t] = h2 * posW[HD + t];
    __syncthreads();
    for (int s = 64; s > 0; s >>= 1) {
        if (t < s) { red0[t] += red0[t + s]; red1[t] += red1[t + s]; }
        __syncthreads();
    }
    if (t < 2) {
        float v = ((t == 0) ? red0[0] : red1[0]) + posb[t];
        rp[t] = v;
        out_t[n * 2 + t] = v;
        g_lp[n * 2 + t] += v;
    }
    __syncthreads();
    if (t < ED) g_din[n * ED + t] = fmaf(rp[0], embW[t * 2], fmaf(rp[1], embW[t * 2 + 1], embb[t]));
    if (t < 64) {
        int mb = n >> 7, m = n & 127;
        int c = t >> 5;
        ((uint32_t*)g_mAh)[(size_t)(mb * 18 + c) * 4096 + m * 32 + (t & 31)] =
            pack2hf(hs2[2 * t], hs2[2 * t + 1]);
    }
}

// ---------------- build x1 fp16 tiles (once per step) ----------------
__global__ __launch_bounds__(256) void build_x1() {
    int c = blockIdx.x, ib = blockIdx.y, s = blockIdx.z;
    int tid = threadIdx.x;
    __shared__ float rxs[128], rys[128];
    if (tid < 128) {
        int i = ib * 4 + (tid >> 5), j = tid & 31;
        float dx = g_lp[(s * 32 + j) * 2]     - g_lp[(s * 32 + i) * 2];
        float dy = g_lp[(s * 32 + j) * 2 + 1] - g_lp[(s * 32 + i) * 2 + 1];
        float nrm = fmaxf(sqrtf(dx * dx + dy * dy), 1e-12f);
        rxs[tid] = dx / nrm; rys[tid] = dy / nrm;
    }
    __syncthreads();
    int grp = s * 8 + ib;
    uint32_t* oh = (uint32_t*)g_x1h + (size_t)(grp * 8 + c) * 4096;
    int kp = tid & 31, k = c * 64 + kp * 2;
    float2 ab0 = *(const float2*)(g_A + k);
    float2 bb0 = *(const float2*)(g_B + k);
#pragma unroll
    for (int q = 0; q < 16; q++) {
        int m = (tid >> 5) + q * 8;
        int pj = s * 32 + (m & 31);
        float rx = rxs[m], ry = rys[m];
        float2 hp = *(const float2*)(g_hpre + (size_t)pj * B1D + k);
        float v0 = fmaxf(hp.x + rx * ab0.x + ry * bb0.x, 0.f);
        float v1 = fmaxf(hp.y + rx * ab0.y + ry * bb0.y, 0.f);
        oh[m * 32 + kp] = pack2hf(v0, v1);
    }
}

// ---------------- wmma fp16 2-pass GEMM with cp.async pipeline ----------------
// GM=0: pool, grid(8 nb, 128), GROUPS=2 (M=2x128), KC=16, warp tile 32x64
// GM=1: m1,   grid(8 nb, 16),  GROUPS=1, ROWS=64, KC=36, warp tile 32x32
// GM=2: m2,   grid(4 ksl, 8),  GROUPS=1, ROWS=128, KC=8, warp tile 32x64
template <int GM>
__global__ __launch_bounds__(256) void wmma_gemm() {
    constexpr int KC = (GM == 0) ? 16 : (GM == 1) ? 36 : 8;
    constexpr int GROUPS = (GM == 0) ? 2 : 1;
    constexpr int ROWS = (GM == 1) ? 64 : 128;
    constexpr int NF = (GM == 1) ? 2 : 4;
    constexpr int WC = (GM == 1) ? 4 : 2;
    constexpr int SA = ROWS * 80;                 // bytes per A stage array
    constexpr int SS = GROUPS * SA + 20480;       // stage size (A groups + Wh + Wl)
    extern __shared__ __align__(16) char smraw[];
    uint32_t base = smem_u32(smraw);
    float* c_s = (float*)smraw;

    int tid = threadIdx.x, w = tid >> 5;
    int wr = w / WC, wc = w % WC;                  // warp row/col block
    int nbX = blockIdx.x, grpY = blockIdx.y;

    const __half* Ah_g = (GM == 0) ? g_x1h : (GM == 1) ? g_mAh : g_mBh;
    const __half* Wh_g = (GM == 0) ? g_W2th : (GM == 1) ? g_M1th : g_M2th;
    const __half* Wl_g = (GM == 0) ? g_W2tl : (GM == 1) ? g_M1tl : g_M2tl;

    auto stage = [&](int buf, int c) {
        int tile0 = 0, tile1 = 0, sub, roff = 0, wtile;
        if (GM == 0) {
            int ch = c >> 1; sub = c & 1;
            tile0 = (grpY * 2) * 8 + ch; tile1 = (grpY * 2 + 1) * 8 + ch;
            wtile = nbX * 8 + ch;
        } else if (GM == 1) {
            int ch = c >> 1; sub = c & 1;
            tile0 = (grpY >> 1) * 18 + ch; roff = (grpY & 1) * 64;
            wtile = nbX * 18 + ch;
        } else {
            int gch = nbX * 8 + c; sub = gch & 1;
            tile0 = grpY * 16 + (gch >> 1);
            wtile = gch >> 1;
        }
        uint32_t sb = base + buf * SS;
        for (int i = tid; i < GROUPS * ROWS * 4; i += 256) {
            int g = i / (ROWS * 4), r = (i >> 2) % ROWS, seg = i & 3;
            int tile = g ? tile1 : tile0;
            size_t so = (size_t)tile * 8192 + (roff + r) * 64 + sub * 32 + seg * 8;
            cpa(sb + g * SA + r * 80 + seg * 16, Ah_g + so);
        }
        for (int i = tid; i < 1024; i += 256) {
            int r = i >> 3, hl = (i >> 2) & 1, seg = i & 3;
            size_t so = (size_t)wtile * 8192 + r * 64 + sub * 32 + seg * 8;
            cpa(sb + GROUPS * SA + hl * 10240 + r * 80 + seg * 16,
                (hl ? Wl_g : Wh_g) + so);
        }
        CPA_COMMIT();
    };

    wmma::fragment<wmma::accumulator, 16, 16, 16, float> acc[GROUPS][2][NF];
#pragma unroll
    for (int g = 0; g < GROUPS; g++)
#pragma unroll
        for (int mf = 0; mf < 2; mf++)
#pragma unroll
            for (int nf = 0; nf < NF; nf++) wmma::fill_fragment(acc[g][mf][nf], 0.f);

    stage(0, 0);
    for (int c = 0; c < KC; c++) {
        if (c + 1 < KC) { stage((c + 1) & 1, c + 1); CPA_WAIT1(); } else { CPA_WAIT0(); }
        __syncthreads();
        const __half* sbuf = (const __half*)(smraw + (c & 1) * SS);
        const __half* whp = sbuf + (GROUPS * SA) / 2;
        const __half* wlp = whp + 5120;
#pragma unroll
        for (int ks = 0; ks < 2; ks++) {
            wmma::fragment<wmma::matrix_a, 16, 16, 16, __half, wmma::row_major> af[GROUPS][2];
#pragma unroll
            for (int g = 0; g < GROUPS; g++)
#pragma unroll
                for (int mf = 0; mf < 2; mf++)
                    wmma::load_matrix_sync(af[g][mf],
                        sbuf + g * (SA / 2) + (wr * 32 + mf * 16) * 40 + ks * 16, 40);
#pragma unroll
            for (int nf = 0; nf < NF; nf++) {
                wmma::fragment<wmma::matrix_b, 16, 16, 16, __half, wmma::col_major> bh, bl;
                int coff = (wc * NF * 16 + nf * 16) * 40 + ks * 16;
                wmma::load_matrix_sync(bh, whp + coff, 40);
                wmma::load_matrix_sync(bl, wlp + coff, 40);
#pragma unroll
                for (int g = 0; g < GROUPS; g++)
#pragma unroll
                    for (int mf = 0; mf < 2; mf++) {
                        wmma::mma_sync(acc[g][mf][nf], af[g][mf], bh, acc[g][mf][nf]);
                        wmma::mma_sync(acc[g][mf][nf], af[g][mf], bl, acc[g][mf][nf]);
                    }
            }
        }
        __syncthreads();
    }

    // ---- epilogue (per group; c_s reuses stage smem) ----
    for (int g = 0; g < GROUPS; g++) {
        __syncthreads();
#pragma unroll
        for (int mf = 0; mf < 2; mf++)
#pragma unroll
            for (int nf = 0; nf < NF; nf++)
                wmma::store_matrix_sync(c_s + (wr * 32 + mf * 16) * 136 + wc * NF * 16 + nf * 16,
                                        acc[g][mf][nf], 136, wmma::mem_row_major);
        __syncthreads();

        if (GM == 0) {
            int grp = grpY * 2 + g;
            int s = grp >> 3, ib = grp & 7;
            if (tid < 256) {
                int il = tid >> 6, kp0 = tid & 63;
                int cc0 = kp0 * 2;
                float m0 = c_s[(il * 32) * 136 + cc0];
                float m1v = c_s[(il * 32) * 136 + cc0 + 1];
#pragma unroll 8
                for (int r = 1; r < 32; r++) {
                    m0  = fmaxf(m0,  c_s[(il * 32 + r) * 136 + cc0]);
                    m1v = fmaxf(m1v, c_s[(il * 32 + r) * 136 + cc0 + 1]);
                }
                int col = nbX * 128 + cc0;
                float v0 = fmaxf(m0 + g_bias2[col], 0.f);
                float v1 = fmaxf(m1v + g_bias2[col + 1], 0.f);
                int ped = s * 32 + ib * 4 + il;
                int mb = ped >> 7, m = ped & 127;
                int cch = 2 + nbX * 2 + (kp0 >> 5);
                ((uint32_t*)g_mAh)[(size_t)(mb * 18 + cch) * 4096 + m * 32 + (kp0 & 31)] =
                    pack2hf(v0, v1);
            }
        } else if (GM == 1) {
            for (int p = tid; p < 4096; p += 256) {
                int r = p >> 6, kp = p & 63;
                int cc0 = kp * 2, col = nbX * 128 + cc0;
                float v0 = fmaxf(c_s[r * 136 + cc0]     + g_bm1[col], 0.f);
                float v1 = fmaxf(c_s[r * 136 + cc0 + 1] + g_bm1[col + 1], 0.f);
                int ped = grpY * 64 + r;
                int mb = ped >> 7, m = ped & 127;
                int cch = nbX * 2 + (kp >> 5);
                ((uint32_t*)g_mBh)[(size_t)(mb * 16 + cch) * 4096 + m * 32 + (kp & 31)] =
                    pack2hf(v0, v1);
            }
        } else {
            float* dst = g_hp + (size_t)nbX * NT * HD + (size_t)grpY * 128 * HD;
            for (int p = tid; p < 16384; p += 256) {
                int r = p >> 7, cc = p & 127;
                dst[r * HD + cc] = c_s[r * 136 + cc];
            }
        }
    }
}

// ---------------- host launch ----------------
extern "C" void kernel_launch(void* const* d_in, const int* in_sizes, int n_in,
                              void* d_out, int out_size) {
    const float* last_pos     = (const float*)d_in[0];
    const float* last_pos_rel = (const float*)d_in[1];
    const float* h0  = (const float*)d_in[2];
    const float* c0  = (const float*)d_in[3];
    const float* emb_W = (const float*)d_in[5];
    const float* emb_b = (const float*)d_in[6];
    const float* Wih = (const float*)d_in[7];
    const float* Whh = (const float*)d_in[8];
    const float* bih = (const float*)d_in[9];
    const float* bhh = (const float*)d_in[10];
    const float* pos_W = (const float*)d_in[11];
    const float* pos_b = (const float*)d_in[12];
    const float* sp_W = (const float*)d_in[13];
    const float* sp_b = (const float*)d_in[14];
    const float* pp1_W = (const float*)d_in[15];
    const float* pp1_b = (const float*)d_in[16];
    const float* pp1_g = (const float*)d_in[17];
    const float* pp1_be = (const float*)d_in[18];
    const float* pp2_W = (const float*)d_in[19];
    const float* pp2_b = (const float*)d_in[20];
    const float* pp2_g = (const float*)d_in[21];
    const float* pp2_be = (const float*)d_in[22];
    const float* m1_W = (const float*)d_in[23];
    const float* m1_b = (const float*)d_in[24];
    const float* m1_g = (const float*)d_in[25];
    const float* m1_be = (const float*)d_in[26];
    const float* m2_W = (const float*)d_in[27];
    const float* m2_b = (const float*)d_in[28];
    const float* m2_g = (const float*)d_in[29];
    const float* m2_be = (const float*)d_in[30];
    float* out = (float*)d_out;

    cudaFuncSetAttribute(wmma_gemm<0>, cudaFuncAttributeMaxDynamicSharedMemorySize, 81920);
    cudaFuncSetAttribute(wmma_gemm<1>, cudaFuncAttributeMaxDynamicSharedMemorySize, 51200);
    cudaFuncSetAttribute(wmma_gemm<2>, cudaFuncAttributeMaxDynamicSharedMemorySize, 69632);

    init_state<<<(NT * HD + 255) / 256, 256>>>(h0, c0, last_pos, last_pos_rel, emb_W, emb_b);
    fold_pp1<<<2, 256>>>(pp1_W, pp1_b, pp1_g, pp1_be, sp_W, sp_b);
    fold_LW<<<96, 256>>>(Wih, Whh, bih, bhh);
    prep_wB<0><<<512, 256>>>(pp2_W, pp2_b, pp2_g, pp2_be);
    prep_wB<1><<<512, 256>>>(m1_W, m1_b, m1_g, m1_be);
    prep_wB<2><<<128, 256>>>(m2_W, m2_b, m2_g, m2_be);

    for (int t = 0; t < TS; t++) {
        if (t == 0) tile_gemm<2, 1><<<dim3(4, NT / 32), 256>>>();  // gates (h from h0)
        else        tile_gemm<2, 0><<<dim3(4, NT / 32), 256>>>();  // gates (h = relu(sum hp + bm2))
        lstm_point<<<NT, 128>>>(pos_W, pos_b, emb_W, emb_b, out + (size_t)t * NT * 2);
        tile_gemm<0, 0><<<dim3(4, NT / 32), 256>>>();              // hpre
        build_x1<<<dim3(8, 8, SC), 256>>>();                       // x1 fp16 tiles
        wmma_gemm<0><<<dim3(8, 128), 256, 81920>>>();              // pool (2 M-groups/CTA)
        wmma_gemm<1><<<dim3(8, 16), 256, 51200>>>();               // m1
        wmma_gemm<2><<<dim3(4, 8), 256, 69632>>>();                // m2 split-K partials
    }
    (void)in_sizes; (void)n_in; (void)out_size;
}

// round 9
// speedup vs baseline: 8.2917x; 1.4210x over previous
#include <cuda_runtime.h>
#include <cuda_fp16.h>
#include <mma.h>
#include <stdint.h>
#include <math.h>

using namespace nvcuda;

#define NT 1024
#define HD 128
#define ED 64
#define SC 32
#define PP 32
#define B1D 512
#define B2D 1024
#define M1D 1024
#define TS 12
#define KM1 (HD + B2D)   // 1152
#define BN_INV_F 0.9999950000374997f

// ---------------- device state / scratch ----------------
static __device__ float g_h[NT * HD];
static __device__ float g_c[NT * HD];
static __device__ float g_h2[NT * HD];
static __device__ float g_lp[NT * 2];
static __device__ float g_din[NT * ED];
static __device__ float g_hpre[NT * B1D];
static __device__ float g_gates[NT * 4 * HD];
static __device__ float g_hp[4 * NT * HD];     // m2 split-K partials
// folded scalar weights
static __device__ float g_A[B1D], g_B[B1D], g_bias1[B1D];
static __device__ float g_Wb[B1D * HD];
static __device__ float g_bias2[B2D], g_bm1[M1D], g_bm2[HD];
static __device__ float g_LW[4 * HD * 192], g_Lb[4 * HD];
// pre-tiled fp16 weights: [nb][chunk64][128r x 64k] tiles (8192 halfs)
static __device__ __half g_W2th[8 * 8 * 8192];
static __device__ __half g_M1th[8 * 18 * 8192];
static __device__ __half g_M2th[16 * 8192];
// activation tiles, fp16, [group][chunk64][128x64]
static __device__ __half g_x1h[256 * 8 * 8192];   // pool A
static __device__ __half g_mAh[8 * 18 * 8192];    // m1 A
static __device__ __half g_mBh[8 * 16 * 8192];    // m2 A

// ---------------- helpers ----------------
__device__ __forceinline__ uint32_t pack2hf(float v0, float v1) {
    __half2 h = __floats2half2_rn(v0, v1);
    return *(uint32_t*)&h;
}
__device__ __forceinline__ uint32_t smem_u32(const void* p) {
    uint32_t a;
    asm("{ .reg .u64 t; cvta.to.shared.u64 t, %1; cvt.u32.u64 %0, t; }" : "=r"(a) : "l"(p));
    return a;
}
__device__ __forceinline__ void cpa(uint32_t dsmem, const void* gsrc) {
    asm volatile("cp.async.cg.shared.global [%0], [%1], 16;" :: "r"(dsmem), "l"(gsrc) : "memory");
}
#define CPA_COMMIT() asm volatile("cp.async.commit_group;" ::: "memory")
#define CPA_WAIT1()  asm volatile("cp.async.wait_group 1;" ::: "memory")
#define CPA_WAIT0()  asm volatile("cp.async.wait_group 0;" ::: "memory")

// ---------------- prep kernels (once per launch) ----------------
__global__ void init_state(const float* __restrict__ h0, const float* __restrict__ c0,
                           const float* __restrict__ last_pos, const float* __restrict__ last_pos_rel,
                           const float* __restrict__ embW, const float* __restrict__ embb) {
    int idx = blockIdx.x * blockDim.x + threadIdx.x;
    if (idx < NT * HD) { g_h[idx] = h0[idx]; g_c[idx] = c0[idx]; }
    if (idx < NT * 2) g_lp[idx] = last_pos[idx];
    if (idx < NT * ED) {
        int n = idx / ED, e = idx % ED;
        g_din[idx] = last_pos_rel[n * 2] * embW[e * 2] +
                     last_pos_rel[n * 2 + 1] * embW[e * 2 + 1] + embb[e];
    }
}

__global__ void fold_pp1(const float* __restrict__ pp1_W, const float* __restrict__ pp1_b,
                         const float* __restrict__ pp1_g, const float* __restrict__ pp1_be,
                         const float* __restrict__ sp_W, const float* __restrict__ sp_b) {
    int k = blockIdx.x * blockDim.x + threadIdx.x;
    if (k >= B1D) return;
    float s1 = BN_INV_F * pp1_g[k];
    const float* row = pp1_W + (size_t)k * (ED + HD);
    float sa = 0.f, sb = 0.f, sc = 0.f;
    for (int e = 0; e < ED; e++) {
        float w = row[e];
        sa += w * sp_W[e * 2]; sb += w * sp_W[e * 2 + 1]; sc += w * sp_b[e];
    }
    g_A[k] = sa * s1; g_B[k] = sb * s1;
    g_bias1[k] = (pp1_b[k] + sc) * s1 + pp1_be[k];
    for (int h = 0; h < HD; h++) g_Wb[k * HD + h] = row[ED + h] * s1;
}

__global__ void fold_LW(const float* __restrict__ Wih, const float* __restrict__ Whh,
                        const float* __restrict__ bih, const float* __restrict__ bhh) {
    for (int idx = blockIdx.x * blockDim.x + threadIdx.x; idx < 512 * 192; idx += gridDim.x * blockDim.x) {
        int r = idx / 192, cc = idx % 192;
        g_LW[idx] = (cc < 64) ? Wih[r * 64 + cc] : Whh[r * 128 + cc - 64];
        if (cc == 0) g_Lb[r] = bih[r] + bhh[r];
    }
}

// fp16 pre-tiled weights. WM=0: W2(K=512), 1: m1(K=1152), 2: m2(K=1024,R=128)
template <int WM>
__global__ void prep_wB(const float* __restrict__ W, const float* __restrict__ b,
                        const float* __restrict__ g, const float* __restrict__ be) {
    constexpr int K = (WM == 0) ? B1D : (WM == 1) ? KM1 : M1D;
    constexpr int ROWS = (WM == 2) ? HD : 1024;
    constexpr int KC = K / 64;
    __half* oh = (WM == 0) ? g_W2th : (WM == 1) ? g_M1th : g_M2th;
    float* bo = (WM == 0) ? g_bias2 : (WM == 1) ? g_bm1 : g_bm2;
    int total = ROWS * (K / 2);
    for (int p = blockIdx.x * blockDim.x + threadIdx.x; p < total; p += gridDim.x * blockDim.x) {
        int co = p / (K / 2), kp = p % (K / 2), k = kp * 2;
        int nb = co >> 7, r = co & 127, c = k >> 6;
        float s = BN_INV_F * g[co];
        float v0 = W[(size_t)co * K + k] * s, v1 = W[(size_t)co * K + k + 1] * s;
        size_t woff = (size_t)(nb * KC + c) * 4096 + r * 32 + (kp & 31);
        ((uint32_t*)oh)[woff] = pack2hf(v0, v1);
        if (kp == 0) bo[co] = b[co] * s + be[co];
    }
}

// ---------------- SIMT GEMM: MODE 0 hpre(K=128), MODE 2 gates(K=192) ----------------
template <int MODE, int FIRST>
__global__ __launch_bounds__(256) void tile_gemm() {
    constexpr int K = (MODE == 0) ? HD : 192;
    constexpr int LDC = (MODE == 0) ? B1D : 512;
    const float* Wp = (MODE == 0) ? g_Wb : g_LW;
    const float* bp = (MODE == 0) ? g_bias1 : g_Lb;
    float* outp = (MODE == 0) ? g_hpre : g_gates;
    int c0 = blockIdx.x * 128, grp = blockIdx.y, tid = threadIdx.x;
    int tx = tid & 31, ty = tid >> 5;
    __shared__ float a_s[32][64];
    __shared__ float w_s[64][129];
    int nbase = grp * 32;
    float acc[4][4] = {};
    for (int k0 = 0; k0 < K; k0 += 64) {
        __syncthreads();
        for (int idx = tid; idx < 32 * 64; idx += 256) {
            int j = idx >> 6, k = idx & 63, kk = k0 + k;
            float v;
            if (MODE == 0) v = g_h2[(nbase + j) * HD + kk];
            else if (kk < 64) v = g_din[(nbase + j) * ED + kk];
            else {
                int ped = nbase + j, cc = kk - 64;
                if (FIRST) v = g_h[ped * HD + cc];
                else {
                    float sum = g_hp[(size_t)ped * HD + cc]
                              + g_hp[(size_t)(NT + ped) * HD + cc]
                              + g_hp[(size_t)(2 * NT + ped) * HD + cc]
                              + g_hp[(size_t)(3 * NT + ped) * HD + cc];
                    v = fmaxf(sum + g_bm2[cc], 0.f);
                }
            }
            a_s[j][k] = v;
        }
        for (int idx = tid; idx < 128 * 64; idx += 256) {
            int c = idx >> 6, k = idx & 63;
            w_s[k][c] = Wp[(size_t)(c0 + c) * K + k0 + k];
        }
        __syncthreads();
#pragma unroll 4
        for (int k = 0; k < 64; k++) {
            float xr[4], wr[4];
#pragma unroll
            for (int jj = 0; jj < 4; jj++) xr[jj] = a_s[ty + jj * 8][k];
#pragma unroll
            for (int cc = 0; cc < 4; cc++) wr[cc] = w_s[k][tx + cc * 32];
#pragma unroll
            for (int jj = 0; jj < 4; jj++)
#pragma unroll
                for (int cc = 0; cc < 4; cc++) acc[jj][cc] = fmaf(xr[jj], wr[cc], acc[jj][cc]);
        }
    }
#pragma unroll
    for (int jj = 0; jj < 4; jj++) {
        int n = nbase + ty + jj * 8;
#pragma unroll
        for (int cc = 0; cc < 4; cc++) {
            int c = c0 + tx + cc * 32;
            outp[(size_t)n * LDC + c] = acc[jj][cc] + bp[c];
        }
    }
}

// ---------------- LSTM pointwise + h2 pack into m1 A-tiles ----------------
__global__ __launch_bounds__(128) void lstm_point(
    const float* __restrict__ posW, const float* __restrict__ posb,
    const float* __restrict__ embW, const float* __restrict__ embb,
    float* __restrict__ out_t) {
    int n = blockIdx.x, t = threadIdx.x;
    __shared__ float red0[HD], red1[HD], hs2[HD], rp[2];
    float gi = g_gates[n * 512 + 0 * HD + t];
    float gf = g_gates[n * 512 + 1 * HD + t];
    float gg = g_gates[n * 512 + 2 * HD + t];
    float go = g_gates[n * 512 + 3 * HD + t];
    float ig = 1.f / (1.f + expf(-gi));
    float fg = 1.f / (1.f + expf(-gf));
    float gv = tanhf(gg);
    float og = 1.f / (1.f + expf(-go));
    float c2 = fg * g_c[n * HD + t] + ig * gv;
    float h2 = og * tanhf(c2);
    g_c[n * HD + t] = c2;
    g_h2[n * HD + t] = h2;
    hs2[t] = h2;
    red0[t] = h2 * posW[t]; red1[t] = h2 * posW[HD + t];
    __syncthreads();
    for (int s = 64; s > 0; s >>= 1) {
        if (t < s) { red0[t] += red0[t + s]; red1[t] += red1[t + s]; }
        __syncthreads();
    }
    if (t < 2) {
        float v = ((t == 0) ? red0[0] : red1[0]) + posb[t];
        rp[t] = v;
        out_t[n * 2 + t] = v;
        g_lp[n * 2 + t] += v;
    }
    __syncthreads();
    if (t < ED) g_din[n * ED + t] = fmaf(rp[0], embW[t * 2], fmaf(rp[1], embW[t * 2 + 1], embb[t]));
    if (t < 64) {
        int mb = n >> 7, m = n & 127;
        int c = t >> 5;
        ((uint32_t*)g_mAh)[(size_t)(mb * 18 + c) * 4096 + m * 32 + (t & 31)] =
            pack2hf(hs2[2 * t], hs2[2 * t + 1]);
    }
}

// ---------------- build x1 fp16 tiles (once per step) ----------------
__global__ __launch_bounds__(256) void build_x1() {
    int c = blockIdx.x, ib = blockIdx.y, s = blockIdx.z;
    int tid = threadIdx.x;
    __shared__ float rxs[128], rys[128];
    if (tid < 128) {
        int i = ib * 4 + (tid >> 5), j = tid & 31;
        float dx = g_lp[(s * 32 + j) * 2]     - g_lp[(s * 32 + i) * 2];
        float dy = g_lp[(s * 32 + j) * 2 + 1] - g_lp[(s * 32 + i) * 2 + 1];
        float nrm = fmaxf(sqrtf(dx * dx + dy * dy), 1e-12f);
        rxs[tid] = dx / nrm; rys[tid] = dy / nrm;
    }
    __syncthreads();
    int grp = s * 8 + ib;
    uint32_t* oh = (uint32_t*)g_x1h + (size_t)(grp * 8 + c) * 4096;
    int kp = tid & 31, k = c * 64 + kp * 2;
    float2 ab0 = *(const float2*)(g_A + k);
    float2 bb0 = *(const float2*)(g_B + k);
#pragma unroll
    for (int q = 0; q < 16; q++) {
        int m = (tid >> 5) + q * 8;
        int pj = s * 32 + (m & 31);
        float rx = rxs[m], ry = rys[m];
        float2 hp = *(const float2*)(g_hpre + (size_t)pj * B1D + k);
        float v0 = fmaxf(hp.x + rx * ab0.x + ry * bb0.x, 0.f);
        float v1 = fmaxf(hp.y + rx * ab0.y + ry * bb0.y, 0.f);
        oh[m * 32 + kp] = pack2hf(v0, v1);
    }
}

// ---------------- wmma fp16 single-pass GEMM with cp.async pipeline ----------------
// GM=0: pool, grid(8 nb, 128), GROUPS=2 (M=2x128), KC=16, warp tile 32x64
// GM=1: m1,   grid(8 nb, 16),  GROUPS=1, ROWS=64, KC=36, warp tile 32x32
// GM=2: m2,   grid(4 ksl, 8),  GROUPS=1, ROWS=128, KC=8, warp tile 32x64
template <int GM>
__global__ __launch_bounds__(256) void wmma_gemm() {
    constexpr int KC = (GM == 0) ? 16 : (GM == 1) ? 36 : 8;
    constexpr int GROUPS = (GM == 0) ? 2 : 1;
    constexpr int ROWS = (GM == 1) ? 64 : 128;
    constexpr int NF = (GM == 1) ? 2 : 4;
    constexpr int WC = (GM == 1) ? 4 : 2;
    constexpr int SA = ROWS * 80;                 // bytes per A stage array
    constexpr int SS = GROUPS * SA + 10240;       // stage: A groups + Wh
    extern __shared__ __align__(16) char smraw[];
    uint32_t base = smem_u32(smraw);
    float* c_s = (float*)smraw;

    int tid = threadIdx.x, w = tid >> 5;
    int wr = w / WC, wc = w % WC;                  // warp row/col block
    int nbX = blockIdx.x, grpY = blockIdx.y;

    const __half* Ah_g = (GM == 0) ? g_x1h : (GM == 1) ? g_mAh : g_mBh;
    const __half* Wh_g = (GM == 0) ? g_W2th : (GM == 1) ? g_M1th : g_M2th;

    auto stage = [&](int buf, int c) {
        int tile0 = 0, tile1 = 0, sub, roff = 0, wtile;
        if (GM == 0) {
            int ch = c >> 1; sub = c & 1;
            tile0 = (grpY * 2) * 8 + ch; tile1 = (grpY * 2 + 1) * 8 + ch;
            wtile = nbX * 8 + ch;
        } else if (GM == 1) {
            int ch = c >> 1; sub = c & 1;
            tile0 = (grpY >> 1) * 18 + ch; roff = (grpY & 1) * 64;
            wtile = nbX * 18 + ch;
        } else {
            int gch = nbX * 8 + c; sub = gch & 1;
            tile0 = grpY * 16 + (gch >> 1);
            wtile = gch >> 1;
        }
        uint32_t sb = base + buf * SS;
        for (int i = tid; i < GROUPS * ROWS * 4; i += 256) {
            int g = i / (ROWS * 4), r = (i >> 2) % ROWS, seg = i & 3;
            int tile = g ? tile1 : tile0;
            size_t so = (size_t)tile * 8192 + (roff + r) * 64 + sub * 32 + seg * 8;
            cpa(sb + g * SA + r * 80 + seg * 16, Ah_g + so);
        }
        for (int i = tid; i < 512; i += 256) {
            int r = i >> 2, seg = i & 3;
            size_t so = (size_t)wtile * 8192 + r * 64 + sub * 32 + seg * 8;
            cpa(sb + GROUPS * SA + r * 80 + seg * 16, Wh_g + so);
        }
        CPA_COMMIT();
    };

    wmma::fragment<wmma::accumulator, 16, 16, 16, float> acc[GROUPS][2][NF];
#pragma unroll
    for (int g = 0; g < GROUPS; g++)
#pragma unroll
        for (int mf = 0; mf < 2; mf++)
#pragma unroll
            for (int nf = 0; nf < NF; nf++) wmma::fill_fragment(acc[g][mf][nf], 0.f);

    stage(0, 0);
    for (int c = 0; c < KC; c++) {
        if (c + 1 < KC) { stage((c + 1) & 1, c + 1); CPA_WAIT1(); } else { CPA_WAIT0(); }
        __syncthreads();
        const __half* sbuf = (const __half*)(smraw + (c & 1) * SS);
        const __half* whp = sbuf + (GROUPS * SA) / 2;
#pragma unroll
        for (int ks = 0; ks < 2; ks++) {
            wmma::fragment<wmma::matrix_a, 16, 16, 16, __half, wmma::row_major> af[GROUPS][2];
#pragma unroll
            for (int g = 0; g < GROUPS; g++)
#pragma unroll
                for (int mf = 0; mf < 2; mf++)
                    wmma::load_matrix_sync(af[g][mf],
                        sbuf + g * (SA / 2) + (wr * 32 + mf * 16) * 40 + ks * 16, 40);
#pragma unroll
            for (int nf = 0; nf < NF; nf++) {
                wmma::fragment<wmma::matrix_b, 16, 16, 16, __half, wmma::col_major> bh;
                int coff = (wc * NF * 16 + nf * 16) * 40 + ks * 16;
                wmma::load_matrix_sync(bh, whp + coff, 40);
#pragma unroll
                for (int g = 0; g < GROUPS; g++)
#pragma unroll
                    for (int mf = 0; mf < 2; mf++)
                        wmma::mma_sync(acc[g][mf][nf], af[g][mf], bh, acc[g][mf][nf]);
            }
        }
        __syncthreads();
    }

    // ---- epilogue (per group; c_s reuses stage smem) ----
    for (int g = 0; g < GROUPS; g++) {
        __syncthreads();
#pragma unroll
        for (int mf = 0; mf < 2; mf++)
#pragma unroll
            for (int nf = 0; nf < NF; nf++)
                wmma::store_matrix_sync(c_s + (wr * 32 + mf * 16) * 136 + wc * NF * 16 + nf * 16,
                                        acc[g][mf][nf], 136, wmma::mem_row_major);
        __syncthreads();

        if (GM == 0) {
            int grp = grpY * 2 + g;
            int s = grp >> 3, ib = grp & 7;
            if (tid < 256) {
                int il = tid >> 6, kp0 = tid & 63;
                int cc0 = kp0 * 2;
                float m0 = c_s[(il * 32) * 136 + cc0];
                float m1v = c_s[(il * 32) * 136 + cc0 + 1];
#pragma unroll 8
                for (int r = 1; r < 32; r++) {
                    m0  = fmaxf(m0,  c_s[(il * 32 + r) * 136 + cc0]);
                    m1v = fmaxf(m1v, c_s[(il * 32 + r) * 136 + cc0 + 1]);
                }
                int col = nbX * 128 + cc0;
                float v0 = fmaxf(m0 + g_bias2[col], 0.f);
                float v1 = fmaxf(m1v + g_bias2[col + 1], 0.f);
                int ped = s * 32 + ib * 4 + il;
                int mb = ped >> 7, m = ped & 127;
                int cch = 2 + nbX * 2 + (kp0 >> 5);
                ((uint32_t*)g_mAh)[(size_t)(mb * 18 + cch) * 4096 + m * 32 + (kp0 & 31)] =
                    pack2hf(v0, v1);
            }
        } else if (GM == 1) {
            for (int p = tid; p < 4096; p += 256) {
                int r = p >> 6, kp = p & 63;
                int cc0 = kp * 2, col = nbX * 128 + cc0;
                float v0 = fmaxf(c_s[r * 136 + cc0]     + g_bm1[col], 0.f);
                float v1 = fmaxf(c_s[r * 136 + cc0 + 1] + g_bm1[col + 1], 0.f);
                int ped = grpY * 64 + r;
                int mb = ped >> 7, m = ped & 127;
                int cch = nbX * 2 + (kp >> 5);
                ((uint32_t*)g_mBh)[(size_t)(mb * 16 + cch) * 4096 + m * 32 + (kp & 31)] =
                    pack2hf(v0, v1);
            }
        } else {
            float* dst = g_hp + (size_t)nbX * NT * HD + (size_t)grpY * 128 * HD;
            for (int p = tid; p < 16384; p += 256) {
                int r = p >> 7, cc = p & 127;
                dst[r * HD + cc] = c_s[r * 136 + cc];
            }
        }
    }
}

// ---------------- host launch ----------------
extern "C" void kernel_launch(void* const* d_in, const int* in_sizes, int n_in,
                              void* d_out, int out_size) {
    const float* last_pos     = (const float*)d_in[0];
    const float* last_pos_rel = (const float*)d_in[1];
    const float* h0  = (const float*)d_in[2];
    const float* c0  = (const float*)d_in[3];
    const float* emb_W = (const float*)d_in[5];
    const float* emb_b = (const float*)d_in[6];
    const float* Wih = (const float*)d_in[7];
    const float* Whh = (const float*)d_in[8];
    const float* bih = (const float*)d_in[9];
    const float* bhh = (const float*)d_in[10];
    const float* pos_W = (const float*)d_in[11];
    const float* pos_b = (const float*)d_in[12];
    const float* sp_W = (const float*)d_in[13];
    const float* sp_b = (const float*)d_in[14];
    const float* pp1_W = (const float*)d_in[15];
    const float* pp1_b = (const float*)d_in[16];
    const float* pp1_g = (const float*)d_in[17];
    const float* pp1_be = (const float*)d_in[18];
    const float* pp2_W = (const float*)d_in[19];
    const float* pp2_b = (const float*)d_in[20];
    const float* pp2_g = (const float*)d_in[21];
    const float* pp2_be = (const float*)d_in[22];
    const float* m1_W = (const float*)d_in[23];
    const float* m1_b = (const float*)d_in[24];
    const float* m1_g = (const float*)d_in[25];
    const float* m1_be = (const float*)d_in[26];
    const float* m2_W = (const float*)d_in[27];
    const float* m2_b = (const float*)d_in[28];
    const float* m2_g = (const float*)d_in[29];
    const float* m2_be = (const float*)d_in[30];
    float* out = (float*)d_out;

    cudaFuncSetAttribute(wmma_gemm<0>, cudaFuncAttributeMaxDynamicSharedMemorySize, 69632);
    cudaFuncSetAttribute(wmma_gemm<1>, cudaFuncAttributeMaxDynamicSharedMemorySize, 36864);
    cudaFuncSetAttribute(wmma_gemm<2>, cudaFuncAttributeMaxDynamicSharedMemorySize, 69632);

    init_state<<<(NT * HD + 255) / 256, 256>>>(h0, c0, last_pos, last_pos_rel, emb_W, emb_b);
    fold_pp1<<<2, 256>>>(pp1_W, pp1_b, pp1_g, pp1_be, sp_W, sp_b);
    fold_LW<<<96, 256>>>(Wih, Whh, bih, bhh);
    prep_wB<0><<<512, 256>>>(pp2_W, pp2_b, pp2_g, pp2_be);
    prep_wB<1><<<512, 256>>>(m1_W, m1_b, m1_g, m1_be);
    prep_wB<2><<<128, 256>>>(m2_W, m2_b, m2_g, m2_be);

    for (int t = 0; t < TS; t++) {
        if (t == 0) tile_gemm<2, 1><<<dim3(4, NT / 32), 256>>>();  // gates (h from h0)
        else        tile_gemm<2, 0><<<dim3(4, NT / 32), 256>>>();  // gates (h = relu(sum hp + bm2))
        lstm_point<<<NT, 128>>>(pos_W, pos_b, emb_W, emb_b, out + (size_t)t * NT * 2);
        tile_gemm<0, 0><<<dim3(4, NT / 32), 256>>>();              // hpre
        build_x1<<<dim3(8, 8, SC), 256>>>();                       // x1 fp16 tiles
        wmma_gemm<0><<<dim3(8, 128), 256, 69632>>>();              // pool (single-pass fp16)
        wmma_gemm<1><<<dim3(8, 16), 256, 36864>>>();               // m1
        wmma_gemm<2><<<dim3(4, 8), 256, 69632>>>();                // m2 split-K partials
    }
    (void)in_sizes; (void)n_in; (void)out_size;
}